// round 1
// baseline (speedup 1.0000x reference)
#include <cuda_runtime.h>
#include <math.h>

// Problem constants
#define B_    2
#define L_    1024
#define DM_   1024
#define ED_   2048
#define N_    16
#define R_    64
#define K_    4
#define ML_   (B_ * L_)        // 2048 rows
#define F_    (R_ + 2 * N_)    // 96

// ---------------- scratch (device globals; no allocation allowed) ----------
__device__ float g_xz[ML_ * 2 * ED_];    // in_proj output  [2048, 4096]
__device__ float g_xc[ML_ * ED_];        // conv+silu       [2048, 2048]
__device__ float g_dBC[ML_ * F_];        // x_proj output   [2048, 96]
__device__ float g_delta[ML_ * ED_];     // softplus(dt_proj) [2048, 2048]
__device__ float g_ys[ML_ * ED_];        // y * silu(z)     [2048, 2048]

// ---------------- big tiled GEMM: C[M,N] = A[M,K(lda)] * W[N,K]^T ----------
// M,N multiples of 128; K multiple of 16. ACT==1: +bias then softplus.
template <int ACT>
__global__ __launch_bounds__(256, 2) void gemm128(
    const float* __restrict__ A, int lda,
    const float* __restrict__ W,
    const float* __restrict__ bias,
    float* __restrict__ C,
    int M, int N, int K)
{
    __shared__ float As[16][132];
    __shared__ float Ws[16][132];

    const int tid = threadIdx.x;
    const int m0 = blockIdx.y * 128;
    const int n0 = blockIdx.x * 128;
    const int tx = tid & 15;
    const int ty = tid >> 4;

    float acc[8][8];
#pragma unroll
    for (int i = 0; i < 8; i++)
#pragma unroll
        for (int j = 0; j < 8; j++) acc[i][j] = 0.f;

    const int r  = tid >> 2;          // 0..63
    const int c4 = (tid & 3) * 4;     // 0,4,8,12

    for (int k0 = 0; k0 < K; k0 += 16) {
#pragma unroll
        for (int p = 0; p < 2; p++) {
            int row = r + p * 64;
            float4 va = *(const float4*)&A[(size_t)(m0 + row) * lda + k0 + c4];
            As[c4 + 0][row] = va.x; As[c4 + 1][row] = va.y;
            As[c4 + 2][row] = va.z; As[c4 + 3][row] = va.w;
            float4 vw = *(const float4*)&W[(size_t)(n0 + row) * K + k0 + c4];
            Ws[c4 + 0][row] = vw.x; Ws[c4 + 1][row] = vw.y;
            Ws[c4 + 2][row] = vw.z; Ws[c4 + 3][row] = vw.w;
        }
        __syncthreads();

#pragma unroll
        for (int kk = 0; kk < 16; kk++) {
            float a[8], b[8];
#pragma unroll
            for (int i = 0; i < 8; i++) a[i] = As[kk][ty * 8 + i];
#pragma unroll
            for (int j = 0; j < 8; j++) b[j] = Ws[kk][tx * 8 + j];
#pragma unroll
            for (int i = 0; i < 8; i++)
#pragma unroll
                for (int j = 0; j < 8; j++) acc[i][j] = fmaf(a[i], b[j], acc[i][j]);
        }
        __syncthreads();
    }

#pragma unroll
    for (int i = 0; i < 8; i++) {
        int m = m0 + ty * 8 + i;
#pragma unroll
        for (int j = 0; j < 8; j++) {
            int n = n0 + tx * 8 + j;
            float v = acc[i][j];
            if (ACT == 1) {
                v += bias[n];
                v = (v > 20.f) ? v : log1pf(expf(v));   // softplus
            }
            C[(size_t)m * N + n] = v;
        }
    }
}

// ---------------- skinny GEMM: C[M,96] = A[M,K(lda)] * W[96,K]^T -----------
// Tile: 16 rows x 96 cols x 32 k, 256 threads (8x32), TM=2, TN=3.
__global__ __launch_bounds__(256, 4) void gemm_skinny96(
    const float* __restrict__ A, int lda,
    const float* __restrict__ W,
    float* __restrict__ C, int M, int K)
{
    __shared__ float As[32][17];
    __shared__ float Ws[32][97];

    const int tid = threadIdx.x;
    const int m0 = blockIdx.x * 16;
    const int tx = tid & 31;
    const int ty = tid >> 5;

    float acc[2][3] = {{0.f, 0.f, 0.f}, {0.f, 0.f, 0.f}};

    for (int k0 = 0; k0 < K; k0 += 32) {
        if (tid < 128) {                      // A tile: 16 x 32 = 128 float4
            int rr = tid >> 3, cc = (tid & 7) * 4;
            float4 va = *(const float4*)&A[(size_t)(m0 + rr) * lda + k0 + cc];
            As[cc + 0][rr] = va.x; As[cc + 1][rr] = va.y;
            As[cc + 2][rr] = va.z; As[cc + 3][rr] = va.w;
        }
#pragma unroll
        for (int i = 0; i < 3; i++) {         // W tile: 96 x 32 = 768 float4
            int idx = tid + i * 256;
            int rr = idx >> 3, cc = (idx & 7) * 4;
            float4 vw = *(const float4*)&W[(size_t)rr * K + k0 + cc];
            Ws[cc + 0][rr] = vw.x; Ws[cc + 1][rr] = vw.y;
            Ws[cc + 2][rr] = vw.z; Ws[cc + 3][rr] = vw.w;
        }
        __syncthreads();

#pragma unroll
        for (int kk = 0; kk < 32; kk++) {
            float a0 = As[kk][ty * 2 + 0];
            float a1 = As[kk][ty * 2 + 1];
            float b0 = Ws[kk][tx];
            float b1 = Ws[kk][tx + 32];
            float b2 = Ws[kk][tx + 64];
            acc[0][0] = fmaf(a0, b0, acc[0][0]);
            acc[0][1] = fmaf(a0, b1, acc[0][1]);
            acc[0][2] = fmaf(a0, b2, acc[0][2]);
            acc[1][0] = fmaf(a1, b0, acc[1][0]);
            acc[1][1] = fmaf(a1, b1, acc[1][1]);
            acc[1][2] = fmaf(a1, b2, acc[1][2]);
        }
        __syncthreads();
    }

#pragma unroll
    for (int i = 0; i < 2; i++) {
        int m = m0 + ty * 2 + i;
#pragma unroll
        for (int j = 0; j < 3; j++)
            C[(size_t)m * F_ + tx + j * 32] = acc[i][j];
    }
}

// ---------------- causal depthwise conv (K=4) + silu -----------------------
__global__ void conv_silu_kernel(const float* __restrict__ xz,
                                 const float* __restrict__ w,
                                 float* __restrict__ xc)
{
    int idx = blockIdx.x * blockDim.x + threadIdx.x;   // over ML_*ED_
    int e  = idx & (ED_ - 1);
    int bl = idx >> 11;                                 // ED_ = 2048
    int l  = bl & (L_ - 1);

    float acc = 0.f;
#pragma unroll
    for (int k = 0; k < 4; k++) {
        int ls = l - 3 + k;
        if (ls >= 0)
            acc = fmaf(w[e * 4 + k], xz[(size_t)(bl - 3 + k) * (2 * ED_) + e], acc);
    }
    xc[idx] = acc / (1.f + __expf(-acc));   // silu
}

// ---------------- selective scan ------------------------------------------
// One warp = 2 channels (b,e). Lanes 0-15: channel A state n=0..15; 16-31: B.
__global__ __launch_bounds__(256) void scan_kernel(
    const float* __restrict__ xz,     // for z (cols ED_..2ED_)
    const float* __restrict__ xc,
    const float* __restrict__ dBC,
    const float* __restrict__ delta,
    const float* __restrict__ A_log,
    const float* __restrict__ Dp,
    float* __restrict__ ys)
{
    int gw   = (blockIdx.x * blockDim.x + threadIdx.x) >> 5;  // 0..2047
    int lane = threadIdx.x & 31;
    int half = lane >> 4;
    int n    = lane & 15;
    int ch   = gw * 2 + half;          // 0..4095
    int b    = ch >> 11;               // ED_ = 2048
    int e    = ch & (ED_ - 1);

    const float a = -expf(A_log[e * N_ + n]);
    const float d = Dp[e];
    float h = 0.f;

    size_t baseRow = (size_t)b * L_;
    for (int l = 0; l < L_; l++) {
        size_t row = baseRow + l;
        float dl  = delta[row * ED_ + e];
        float xcv = xc[row * ED_ + e];
        float Bv  = dBC[row * F_ + R_ + n];
        float Cv  = dBC[row * F_ + R_ + N_ + n];
        float dA  = __expf(dl * a);
        h = fmaf(h, dA, dl * Bv * xcv);
        float p = h * Cv;
        p += __shfl_xor_sync(0xffffffffu, p, 1);
        p += __shfl_xor_sync(0xffffffffu, p, 2);
        p += __shfl_xor_sync(0xffffffffu, p, 4);
        p += __shfl_xor_sync(0xffffffffu, p, 8);
        if (n == 0) {
            float y  = p + d * xcv;
            float zv = xz[row * (2 * ED_) + ED_ + e];
            float sz = zv / (1.f + __expf(-zv));
            ys[row * ED_ + e] = y * sz;
        }
    }
}

// ---------------- launch ----------------------------------------------------
extern "C" void kernel_launch(void* const* d_in, const int* in_sizes, int n_in,
                              void* d_out, int out_size)
{
    const float* x         = (const float*)d_in[0];
    const float* in_proj_w = (const float*)d_in[1];
    const float* conv_w    = (const float*)d_in[2];
    const float* x_proj_w  = (const float*)d_in[3];
    const float* dt_proj_w = (const float*)d_in[4];
    const float* dt_proj_b = (const float*)d_in[5];
    const float* A_log     = (const float*)d_in[6];
    const float* Dp        = (const float*)d_in[7];
    const float* out_proj_w= (const float*)d_in[8];
    float* out = (float*)d_out;

    float *xz, *xc, *dBC, *delta, *ys;
    cudaGetSymbolAddress((void**)&xz,    g_xz);
    cudaGetSymbolAddress((void**)&xc,    g_xc);
    cudaGetSymbolAddress((void**)&dBC,   g_dBC);
    cudaGetSymbolAddress((void**)&delta, g_delta);
    cudaGetSymbolAddress((void**)&ys,    g_ys);

    // 1) xz = x @ in_proj_w^T          [2048, 4096]
    gemm128<0><<<dim3(2 * ED_ / 128, ML_ / 128), 256>>>(
        x, DM_, in_proj_w, nullptr, xz, ML_, 2 * ED_, DM_);

    // 2) xc = silu(causal depthwise conv(xz[:, :ED]))
    conv_silu_kernel<<<(ML_ * ED_) / 256, 256>>>(xz, conv_w, xc);

    // 3) dBC = xc @ x_proj_w^T          [2048, 96]
    gemm_skinny96<<<ML_ / 16, 256>>>(xc, ED_, x_proj_w, dBC, ML_, ED_);

    // 4) delta = softplus(dBC[:, :64] @ dt_proj_w^T + b)   [2048, 2048]
    gemm128<1><<<dim3(ED_ / 128, ML_ / 128), 256>>>(
        dBC, F_, dt_proj_w, dt_proj_b, delta, ML_, ED_, R_);

    // 5) selective scan -> ys = (y) * silu(z)
    scan_kernel<<<(B_ * ED_ / 2) * 32 / 256, 256>>>(
        xz, xc, dBC, delta, A_log, Dp, ys);

    // 6) out = ys @ out_proj_w^T        [2048, 1024]
    gemm128<0><<<dim3(DM_ / 128, ML_ / 128), 256>>>(
        ys, ED_, out_proj_w, nullptr, out, ML_, DM_, ED_);
}

// round 3
// speedup vs baseline: 1.3021x; 1.3021x over previous
#include <cuda_runtime.h>
#include <cuda_bf16.h>
#include <math.h>
#include <stdint.h>

// Problem constants
#define B_    2
#define L_    1024
#define DM_   1024
#define ED_   2048
#define N_    16
#define R_    64
#define K_    4
#define ML_   (B_ * L_)        // 2048 rows
#define F_    (R_ + 2 * N_)    // 96

// ---------------- scratch (device globals; no allocation allowed) ----------
__device__ float g_xz[ML_ * 2 * ED_];    // in_proj output  [2048, 4096]
__device__ float g_xc[ML_ * ED_];        // conv+silu       [2048, 2048]
__device__ float g_dBC[ML_ * F_];        // x_proj output   [2048, 96]
__device__ float g_delta[ML_ * ED_];     // softplus(dt_proj) [2048, 2048]

// bf16 hi/lo split scratch (16B-aligned for cp.async / vector access)
__device__ __align__(16) __nv_bfloat16 g_xhi[ML_ * DM_];
__device__ __align__(16) __nv_bfloat16 g_xlo[ML_ * DM_];
__device__ __align__(16) __nv_bfloat16 g_wihi[2 * ED_ * DM_];
__device__ __align__(16) __nv_bfloat16 g_wilo[2 * ED_ * DM_];
__device__ __align__(16) __nv_bfloat16 g_yshi[ML_ * ED_];
__device__ __align__(16) __nv_bfloat16 g_yslo[ML_ * ED_];
__device__ __align__(16) __nv_bfloat16 g_wohi[DM_ * ED_];
__device__ __align__(16) __nv_bfloat16 g_wolo[DM_ * ED_];

// ============================================================================
// helpers
// ============================================================================
__device__ __forceinline__ uint32_t smem_u32(const void* p) {
    uint32_t a;
    asm("{ .reg .u64 t; cvta.to.shared.u64 t, %1; cvt.u32.u64 %0, t; }"
        : "=r"(a) : "l"(p));
    return a;
}

__device__ __forceinline__ void cp_async16(uint32_t saddr, const void* gaddr) {
    asm volatile("cp.async.cg.shared.global [%0], [%1], 16;"
                 :: "r"(saddr), "l"(gaddr));
}
#define CP_COMMIT() asm volatile("cp.async.commit_group;" ::: "memory")
#define CP_WAIT(n)  asm volatile("cp.async.wait_group %0;" :: "n"(n) : "memory")

__device__ __forceinline__ void mma16816(float* d, const uint32_t* a,
                                         const uint32_t* b) {
    asm volatile(
        "mma.sync.aligned.m16n8k16.row.col.f32.bf16.bf16.f32 "
        "{%0,%1,%2,%3}, {%4,%5,%6,%7}, {%8,%9}, {%0,%1,%2,%3};"
        : "+f"(d[0]), "+f"(d[1]), "+f"(d[2]), "+f"(d[3])
        : "r"(a[0]), "r"(a[1]), "r"(a[2]), "r"(a[3]),
          "r"(b[0]), "r"(b[1]));
}

// ============================================================================
// bf16-split mma.sync GEMM: C[M,N] = Ahi/lo[M,K] * (Bhi/lo[N,K])^T  (fp32 acc)
// CTA tile 128x128, K staged by 32; 8 warps (2 M x 4 N), warp tile 64x32.
// smem row pitch 40 bf16 (80B) -> conflict-free fragment loads.
// ============================================================================
#define PITCH 40
#define TILE_B (128 * PITCH * 2)          // 10240 B per operand tile
#define STAGE_B (4 * TILE_B)              // 40960 B per K-stage
#define GSM_TOTAL (2 * STAGE_B)           // 81920 B

__global__ __launch_bounds__(256) void gemm_mma_split(
    const __nv_bfloat16* __restrict__ Ahi, const __nv_bfloat16* __restrict__ Alo,
    const __nv_bfloat16* __restrict__ Bhi, const __nv_bfloat16* __restrict__ Blo,
    float* __restrict__ C, int Nc, int K)
{
    extern __shared__ char smem[];

    const int tid  = threadIdx.x;
    const int wid  = tid >> 5;
    const int lane = tid & 31;
    const int gid  = lane >> 2;      // 0..7
    const int tq   = lane & 3;       // 0..3
    const int wm   = (wid >> 2) * 64;    // warp M offset (0/64)
    const int wn   = (wid & 3) * 32;     // warp N offset (0/32/64/96)
    const int m0 = blockIdx.y * 128;
    const int n0 = blockIdx.x * 128;

    const __nv_bfloat16* srcs[4] = {
        Ahi + (size_t)m0 * K, Alo + (size_t)m0 * K,
        Bhi + (size_t)n0 * K, Blo + (size_t)n0 * K };

    const int S = K / 32;

    float acc[4][4][4];
#pragma unroll
    for (int i = 0; i < 4; i++)
#pragma unroll
        for (int j = 0; j < 4; j++)
#pragma unroll
            for (int r = 0; r < 4; r++) acc[i][j][r] = 0.f;

    // ---- async load of one K=32 stage -------------------------------------
    const int lrow = tid >> 2;        // 0..63
    const int lc   = tid & 3;         // 16B chunk 0..3
    auto load_stage = [&](int s, int buf) {
        const int k0 = s * 32;
        char* sb = smem + buf * STAGE_B;
#pragma unroll
        for (int t = 0; t < 4; t++) {
            const __nv_bfloat16* src = srcs[t] + k0 + lc * 8;
            char* tb = sb + t * TILE_B;
#pragma unroll
            for (int i = 0; i < 2; i++) {
                int r = lrow + i * 64;
                cp_async16(smem_u32(tb + r * (PITCH * 2) + lc * 16),
                           src + (size_t)r * K);
            }
        }
    };

    auto lds32 = [](const char* base, int elem) -> uint32_t {
        return *(const uint32_t*)(base + elem * 2);
    };

    // ---- compute one staged K=32 ------------------------------------------
    auto compute = [&](int buf) {
        const char* sb  = smem + buf * STAGE_B;
        const char* sAh = sb;
        const char* sAl = sb + TILE_B;
        const char* sBh = sb + 2 * TILE_B;
        const char* sBl = sb + 3 * TILE_B;
#pragma unroll
        for (int kk = 0; kk < 2; kk++) {
            const int kc = kk * 16 + tq * 2;
            uint32_t ah[4][4], al[4][4];
#pragma unroll
            for (int mt = 0; mt < 4; mt++) {
                int ar = wm + mt * 16 + gid;
                ah[mt][0] = lds32(sAh, ar * PITCH + kc);
                ah[mt][1] = lds32(sAh, (ar + 8) * PITCH + kc);
                ah[mt][2] = lds32(sAh, ar * PITCH + kc + 8);
                ah[mt][3] = lds32(sAh, (ar + 8) * PITCH + kc + 8);
                al[mt][0] = lds32(sAl, ar * PITCH + kc);
                al[mt][1] = lds32(sAl, (ar + 8) * PITCH + kc);
                al[mt][2] = lds32(sAl, ar * PITCH + kc + 8);
                al[mt][3] = lds32(sAl, (ar + 8) * PITCH + kc + 8);
            }
            uint32_t bh[4][2], bl[4][2];
#pragma unroll
            for (int nt = 0; nt < 4; nt++) {
                int br = wn + nt * 8 + gid;
                bh[nt][0] = lds32(sBh, br * PITCH + kc);
                bh[nt][1] = lds32(sBh, br * PITCH + kc + 8);
                bl[nt][0] = lds32(sBl, br * PITCH + kc);
                bl[nt][1] = lds32(sBl, br * PITCH + kc + 8);
            }
#pragma unroll
            for (int mt = 0; mt < 4; mt++)
#pragma unroll
                for (int nt = 0; nt < 4; nt++) {
                    mma16816(acc[mt][nt], ah[mt], bh[nt]);
                    mma16816(acc[mt][nt], ah[mt], bl[nt]);
                    mma16816(acc[mt][nt], al[mt], bh[nt]);
                }
        }
    };

    // ---- pipeline -----------------------------------------------------------
    load_stage(0, 0);
    CP_COMMIT();
    for (int s = 0; s < S; s++) {
        if (s + 1 < S) {
            load_stage(s + 1, (s + 1) & 1);
            CP_COMMIT();
            CP_WAIT(1);
        } else {
            CP_WAIT(0);
        }
        __syncthreads();
        compute(s & 1);
        __syncthreads();
    }

    // ---- epilogue -----------------------------------------------------------
#pragma unroll
    for (int mt = 0; mt < 4; mt++) {
        int row = m0 + wm + mt * 16 + gid;
#pragma unroll
        for (int nt = 0; nt < 4; nt++) {
            int col = n0 + wn + nt * 8 + tq * 2;
            float2 v0 = make_float2(acc[mt][nt][0], acc[mt][nt][1]);
            float2 v1 = make_float2(acc[mt][nt][2], acc[mt][nt][3]);
            *(float2*)&C[(size_t)row * Nc + col] = v0;
            *(float2*)&C[(size_t)(row + 8) * Nc + col] = v1;
        }
    }
}

// ---------------- fp32 -> bf16 hi/lo split ---------------------------------
__global__ void cvt_split_kernel(const float4* __restrict__ src,
                                 __nv_bfloat162* __restrict__ hi,
                                 __nv_bfloat162* __restrict__ lo, int n4)
{
    int i = blockIdx.x * blockDim.x + threadIdx.x;
    if (i >= n4) return;
    float4 v = src[i];
    __nv_bfloat16 h0 = __float2bfloat16(v.x);
    __nv_bfloat16 h1 = __float2bfloat16(v.y);
    __nv_bfloat16 h2 = __float2bfloat16(v.z);
    __nv_bfloat16 h3 = __float2bfloat16(v.w);
    __nv_bfloat16 l0 = __float2bfloat16(v.x - __bfloat162float(h0));
    __nv_bfloat16 l1 = __float2bfloat16(v.y - __bfloat162float(h1));
    __nv_bfloat16 l2 = __float2bfloat16(v.z - __bfloat162float(h2));
    __nv_bfloat16 l3 = __float2bfloat16(v.w - __bfloat162float(h3));
    hi[2 * i]     = __halves2bfloat162(h0, h1);
    hi[2 * i + 1] = __halves2bfloat162(h2, h3);
    lo[2 * i]     = __halves2bfloat162(l0, l1);
    lo[2 * i + 1] = __halves2bfloat162(l2, l3);
}

// ---------------- fp32 tiled GEMM (dt_proj, K=64) + softplus ----------------
template <int ACT>
__global__ __launch_bounds__(256, 2) void gemm128(
    const float* __restrict__ A, int lda,
    const float* __restrict__ W,
    const float* __restrict__ bias,
    float* __restrict__ C,
    int M, int N, int K)
{
    __shared__ float As[16][132];
    __shared__ float Ws[16][132];

    const int tid = threadIdx.x;
    const int m0 = blockIdx.y * 128;
    const int n0 = blockIdx.x * 128;
    const int tx = tid & 15;
    const int ty = tid >> 4;

    float acc[8][8];
#pragma unroll
    for (int i = 0; i < 8; i++)
#pragma unroll
        for (int j = 0; j < 8; j++) acc[i][j] = 0.f;

    const int r  = tid >> 2;
    const int c4 = (tid & 3) * 4;

    for (int k0 = 0; k0 < K; k0 += 16) {
#pragma unroll
        for (int p = 0; p < 2; p++) {
            int row = r + p * 64;
            float4 va = *(const float4*)&A[(size_t)(m0 + row) * lda + k0 + c4];
            As[c4 + 0][row] = va.x; As[c4 + 1][row] = va.y;
            As[c4 + 2][row] = va.z; As[c4 + 3][row] = va.w;
            float4 vw = *(const float4*)&W[(size_t)(n0 + row) * K + k0 + c4];
            Ws[c4 + 0][row] = vw.x; Ws[c4 + 1][row] = vw.y;
            Ws[c4 + 2][row] = vw.z; Ws[c4 + 3][row] = vw.w;
        }
        __syncthreads();

#pragma unroll
        for (int kk = 0; kk < 16; kk++) {
            float a[8], b[8];
#pragma unroll
            for (int i = 0; i < 8; i++) a[i] = As[kk][ty * 8 + i];
#pragma unroll
            for (int j = 0; j < 8; j++) b[j] = Ws[kk][tx * 8 + j];
#pragma unroll
            for (int i = 0; i < 8; i++)
#pragma unroll
                for (int j = 0; j < 8; j++) acc[i][j] = fmaf(a[i], b[j], acc[i][j]);
        }
        __syncthreads();
    }

#pragma unroll
    for (int i = 0; i < 8; i++) {
        int m = m0 + ty * 8 + i;
#pragma unroll
        for (int j = 0; j < 8; j++) {
            int n = n0 + tx * 8 + j;
            float v = acc[i][j];
            if (ACT == 1) {
                v += bias[n];
                v = (v > 20.f) ? v : log1pf(expf(v));
            }
            C[(size_t)m * N + n] = v;
        }
    }
}

// ---------------- skinny GEMM: C[M,96] = A[M,K] * W[96,K]^T -----------------
__global__ __launch_bounds__(256, 4) void gemm_skinny96(
    const float* __restrict__ A, int lda,
    const float* __restrict__ W,
    float* __restrict__ C, int M, int K)
{
    __shared__ float As[32][17];
    __shared__ float Ws[32][97];

    const int tid = threadIdx.x;
    const int m0 = blockIdx.x * 16;
    const int tx = tid & 31;
    const int ty = tid >> 5;

    float acc[2][3] = {{0.f, 0.f, 0.f}, {0.f, 0.f, 0.f}};

    for (int k0 = 0; k0 < K; k0 += 32) {
        if (tid < 128) {
            int rr = tid >> 3, cc = (tid & 7) * 4;
            float4 va = *(const float4*)&A[(size_t)(m0 + rr) * lda + k0 + cc];
            As[cc + 0][rr] = va.x; As[cc + 1][rr] = va.y;
            As[cc + 2][rr] = va.z; As[cc + 3][rr] = va.w;
        }
#pragma unroll
        for (int i = 0; i < 3; i++) {
            int idx = tid + i * 256;
            int rr = idx >> 3, cc = (idx & 7) * 4;
            float4 vw = *(const float4*)&W[(size_t)rr * K + k0 + cc];
            Ws[cc + 0][rr] = vw.x; Ws[cc + 1][rr] = vw.y;
            Ws[cc + 2][rr] = vw.z; Ws[cc + 3][rr] = vw.w;
        }
        __syncthreads();

#pragma unroll
        for (int kk = 0; kk < 32; kk++) {
            float a0 = As[kk][ty * 2 + 0];
            float a1 = As[kk][ty * 2 + 1];
            float b0 = Ws[kk][tx];
            float b1 = Ws[kk][tx + 32];
            float b2 = Ws[kk][tx + 64];
            acc[0][0] = fmaf(a0, b0, acc[0][0]);
            acc[0][1] = fmaf(a0, b1, acc[0][1]);
            acc[0][2] = fmaf(a0, b2, acc[0][2]);
            acc[1][0] = fmaf(a1, b0, acc[1][0]);
            acc[1][1] = fmaf(a1, b1, acc[1][1]);
            acc[1][2] = fmaf(a1, b2, acc[1][2]);
        }
        __syncthreads();
    }

#pragma unroll
    for (int i = 0; i < 2; i++) {
        int m = m0 + ty * 2 + i;
#pragma unroll
        for (int j = 0; j < 3; j++)
            C[(size_t)m * F_ + tx + j * 32] = acc[i][j];
    }
}

// ---------------- causal depthwise conv (K=4) + silu -----------------------
__global__ void conv_silu_kernel(const float* __restrict__ xz,
                                 const float* __restrict__ w,
                                 float* __restrict__ xc)
{
    int idx = blockIdx.x * blockDim.x + threadIdx.x;
    int e  = idx & (ED_ - 1);
    int bl = idx >> 11;
    int l  = bl & (L_ - 1);

    float acc = 0.f;
#pragma unroll
    for (int k = 0; k < 4; k++) {
        int ls = l - 3 + k;
        if (ls >= 0)
            acc = fmaf(w[e * 4 + k], xz[(size_t)(bl - 3 + k) * (2 * ED_) + e], acc);
    }
    xc[idx] = acc / (1.f + __expf(-acc));
}

// ---------------- selective scan (emits ys hi/lo directly) ------------------
__global__ __launch_bounds__(256) void scan_kernel(
    const float* __restrict__ xz,
    const float* __restrict__ xc,
    const float* __restrict__ dBC,
    const float* __restrict__ delta,
    const float* __restrict__ A_log,
    const float* __restrict__ Dp,
    __nv_bfloat16* __restrict__ yshi,
    __nv_bfloat16* __restrict__ yslo)
{
    int gw   = (blockIdx.x * blockDim.x + threadIdx.x) >> 5;
    int lane = threadIdx.x & 31;
    int half = lane >> 4;
    int n    = lane & 15;
    int ch   = gw * 2 + half;
    int b    = ch >> 11;
    int e    = ch & (ED_ - 1);

    const float a = -expf(A_log[e * N_ + n]);
    const float d = Dp[e];
    float h = 0.f;

    size_t baseRow = (size_t)b * L_;
    for (int l = 0; l < L_; l++) {
        size_t row = baseRow + l;
        float dl  = delta[row * ED_ + e];
        float xcv = xc[row * ED_ + e];
        float Bv  = dBC[row * F_ + R_ + n];
        float Cv  = dBC[row * F_ + R_ + N_ + n];
        float dA  = __expf(dl * a);
        h = fmaf(h, dA, dl * Bv * xcv);
        float p = h * Cv;
        p += __shfl_xor_sync(0xffffffffu, p, 1);
        p += __shfl_xor_sync(0xffffffffu, p, 2);
        p += __shfl_xor_sync(0xffffffffu, p, 4);
        p += __shfl_xor_sync(0xffffffffu, p, 8);
        if (n == 0) {
            float y  = p + d * xcv;
            float zv = xz[row * (2 * ED_) + ED_ + e];
            float sz = zv / (1.f + __expf(-zv));
            float v = y * sz;
            __nv_bfloat16 hv = __float2bfloat16(v);
            yshi[row * ED_ + e] = hv;
            yslo[row * ED_ + e] = __float2bfloat16(v - __bfloat162float(hv));
        }
    }
}

// ---------------- launch ----------------------------------------------------
extern "C" void kernel_launch(void* const* d_in, const int* in_sizes, int n_in,
                              void* d_out, int out_size)
{
    const float* x         = (const float*)d_in[0];
    const float* in_proj_w = (const float*)d_in[1];
    const float* conv_w    = (const float*)d_in[2];
    const float* x_proj_w  = (const float*)d_in[3];
    const float* dt_proj_w = (const float*)d_in[4];
    const float* dt_proj_b = (const float*)d_in[5];
    const float* A_log     = (const float*)d_in[6];
    const float* Dp        = (const float*)d_in[7];
    const float* out_proj_w= (const float*)d_in[8];
    float* out = (float*)d_out;

    float *xz, *xc, *dBC, *delta;
    cudaGetSymbolAddress((void**)&xz,    g_xz);
    cudaGetSymbolAddress((void**)&xc,    g_xc);
    cudaGetSymbolAddress((void**)&dBC,   g_dBC);
    cudaGetSymbolAddress((void**)&delta, g_delta);

    __nv_bfloat16 *xhi, *xlo, *wihi, *wilo, *yshi, *yslo, *wohi, *wolo;
    cudaGetSymbolAddress((void**)&xhi,  g_xhi);
    cudaGetSymbolAddress((void**)&xlo,  g_xlo);
    cudaGetSymbolAddress((void**)&wihi, g_wihi);
    cudaGetSymbolAddress((void**)&wilo, g_wilo);
    cudaGetSymbolAddress((void**)&yshi, g_yshi);
    cudaGetSymbolAddress((void**)&yslo, g_yslo);
    cudaGetSymbolAddress((void**)&wohi, g_wohi);
    cudaGetSymbolAddress((void**)&wolo, g_wolo);

    static int smem_set = 0;
    if (!smem_set) {
        cudaFuncSetAttribute(gemm_mma_split,
                             cudaFuncAttributeMaxDynamicSharedMemorySize, GSM_TOTAL);
        smem_set = 1;
    }

    // 0) fp32 -> bf16 hi/lo splits
    cvt_split_kernel<<<(ML_ * DM_ / 4 + 255) / 256, 256>>>(
        (const float4*)x, (__nv_bfloat162*)xhi, (__nv_bfloat162*)xlo, ML_ * DM_ / 4);
    cvt_split_kernel<<<(2 * ED_ * DM_ / 4 + 255) / 256, 256>>>(
        (const float4*)in_proj_w, (__nv_bfloat162*)wihi, (__nv_bfloat162*)wilo,
        2 * ED_ * DM_ / 4);
    cvt_split_kernel<<<(DM_ * ED_ / 4 + 255) / 256, 256>>>(
        (const float4*)out_proj_w, (__nv_bfloat162*)wohi, (__nv_bfloat162*)wolo,
        DM_ * ED_ / 4);

    // 1) xz = x @ in_proj_w^T   [2048, 4096]   (mma.sync bf16-split)
    gemm_mma_split<<<dim3(2 * ED_ / 128, ML_ / 128), 256, GSM_TOTAL>>>(
        xhi, xlo, wihi, wilo, xz, 2 * ED_, DM_);

    // 2) xc = silu(causal depthwise conv(xz[:, :ED]))
    conv_silu_kernel<<<(ML_ * ED_) / 256, 256>>>(xz, conv_w, xc);

    // 3) dBC = xc @ x_proj_w^T   [2048, 96]
    gemm_skinny96<<<ML_ / 16, 256>>>(xc, ED_, x_proj_w, dBC, ML_, ED_);

    // 4) delta = softplus(dBC[:, :64] @ dt_proj_w^T + b)   [2048, 2048]
    gemm128<1><<<dim3(ED_ / 128, ML_ / 128), 256>>>(
        dBC, F_, dt_proj_w, dt_proj_b, delta, ML_, ED_, R_);

    // 5) selective scan -> ys hi/lo = (y * silu(z)) split
    scan_kernel<<<(B_ * ED_ / 2) * 32 / 256, 256>>>(
        xz, xc, dBC, delta, A_log, Dp, yshi, yslo);

    // 6) out = ys @ out_proj_w^T  [2048, 1024]   (mma.sync bf16-split)
    gemm_mma_split<<<dim3(DM_ / 128, ML_ / 128), 256, GSM_TOTAL>>>(
        yshi, yslo, wohi, wolo, out, DM_, ED_);
}

// round 4
// speedup vs baseline: 2.7119x; 2.0826x over previous
#include <cuda_runtime.h>
#include <cuda_bf16.h>
#include <math.h>
#include <stdint.h>

// Problem constants
#define B_    2
#define L_    1024
#define DM_   1024
#define ED_   2048
#define N_    16
#define R_    64
#define K_    4
#define ML_   (B_ * L_)        // 2048 rows
#define F_    (R_ + 2 * N_)    // 96

// ---------------- scratch (device globals; no allocation allowed) ----------
__device__ float g_xz[ML_ * 2 * ED_];    // in_proj output  [2048, 4096]
__device__ float g_xc[ML_ * ED_];        // conv+silu       [2048, 2048]
__device__ float g_dBC[ML_ * F_];        // x_proj output   [2048, 96]
__device__ float g_delta[ML_ * ED_];     // softplus(dt_proj) [2048, 2048]

// bf16 hi/lo split scratch (16B-aligned for cp.async / vector access)
__device__ __align__(16) __nv_bfloat16 g_xhi[ML_ * DM_];
__device__ __align__(16) __nv_bfloat16 g_xlo[ML_ * DM_];
__device__ __align__(16) __nv_bfloat16 g_wihi[2 * ED_ * DM_];
__device__ __align__(16) __nv_bfloat16 g_wilo[2 * ED_ * DM_];
__device__ __align__(16) __nv_bfloat16 g_yshi[ML_ * ED_];
__device__ __align__(16) __nv_bfloat16 g_yslo[ML_ * ED_];
__device__ __align__(16) __nv_bfloat16 g_wohi[DM_ * ED_];
__device__ __align__(16) __nv_bfloat16 g_wolo[DM_ * ED_];

// ============================================================================
// helpers
// ============================================================================
__device__ __forceinline__ uint32_t smem_u32(const void* p) {
    uint32_t a;
    asm("{ .reg .u64 t; cvta.to.shared.u64 t, %1; cvt.u32.u64 %0, t; }"
        : "=r"(a) : "l"(p));
    return a;
}

__device__ __forceinline__ void cp_async16(uint32_t saddr, const void* gaddr) {
    asm volatile("cp.async.cg.shared.global [%0], [%1], 16;"
                 :: "r"(saddr), "l"(gaddr));
}
#define CP_COMMIT() asm volatile("cp.async.commit_group;" ::: "memory")
#define CP_WAIT(n)  asm volatile("cp.async.wait_group %0;" :: "n"(n) : "memory")

__device__ __forceinline__ void mma16816(float* d, const uint32_t* a,
                                         const uint32_t* b) {
    asm volatile(
        "mma.sync.aligned.m16n8k16.row.col.f32.bf16.bf16.f32 "
        "{%0,%1,%2,%3}, {%4,%5,%6,%7}, {%8,%9}, {%0,%1,%2,%3};"
        : "+f"(d[0]), "+f"(d[1]), "+f"(d[2]), "+f"(d[3])
        : "r"(a[0]), "r"(a[1]), "r"(a[2]), "r"(a[3]),
          "r"(b[0]), "r"(b[1]));
}

// ============================================================================
// bf16-split mma.sync GEMM: C[M,N] = Ahi/lo[M,K] * (Bhi/lo[N,K])^T  (fp32 acc)
// CTA tile 128x128, K staged by 32; 8 warps (2 M x 4 N), warp tile 64x32.
// 3-stage cp.async pipeline, one __syncthreads per stage.
// ============================================================================
#define PITCH 40
#define TILE_B (128 * PITCH * 2)          // 10240 B per operand tile
#define STAGE_B (4 * TILE_B)              // 40960 B per K-stage
#define GSM_TOTAL (3 * STAGE_B)           // 122880 B

__global__ __launch_bounds__(256) void gemm_mma_split(
    const __nv_bfloat16* __restrict__ Ahi, const __nv_bfloat16* __restrict__ Alo,
    const __nv_bfloat16* __restrict__ Bhi, const __nv_bfloat16* __restrict__ Blo,
    float* __restrict__ C, int Nc, int K)
{
    extern __shared__ char smem[];

    const int tid  = threadIdx.x;
    const int wid  = tid >> 5;
    const int lane = tid & 31;
    const int gid  = lane >> 2;      // 0..7
    const int tq   = lane & 3;       // 0..3
    const int wm   = (wid >> 2) * 64;    // warp M offset (0/64)
    const int wn   = (wid & 3) * 32;     // warp N offset (0/32/64/96)
    const int m0 = blockIdx.y * 128;
    const int n0 = blockIdx.x * 128;

    const __nv_bfloat16* srcs[4] = {
        Ahi + (size_t)m0 * K, Alo + (size_t)m0 * K,
        Bhi + (size_t)n0 * K, Blo + (size_t)n0 * K };

    const int S = K / 32;

    float acc[4][4][4];
#pragma unroll
    for (int i = 0; i < 4; i++)
#pragma unroll
        for (int j = 0; j < 4; j++)
#pragma unroll
            for (int r = 0; r < 4; r++) acc[i][j][r] = 0.f;

    const int lrow = tid >> 2;        // 0..63
    const int lc   = tid & 3;         // 16B chunk 0..3
    auto load_stage = [&](int s, int buf) {
        const int k0 = s * 32;
        char* sb = smem + buf * STAGE_B;
#pragma unroll
        for (int t = 0; t < 4; t++) {
            const __nv_bfloat16* src = srcs[t] + k0 + lc * 8;
            char* tb = sb + t * TILE_B;
#pragma unroll
            for (int i = 0; i < 2; i++) {
                int r = lrow + i * 64;
                cp_async16(smem_u32(tb + r * (PITCH * 2) + lc * 16),
                           src + (size_t)r * K);
            }
        }
    };

    auto lds32 = [](const char* base, int elem) -> uint32_t {
        return *(const uint32_t*)(base + elem * 2);
    };

    auto compute = [&](int buf) {
        const char* sb  = smem + buf * STAGE_B;
        const char* sAh = sb;
        const char* sAl = sb + TILE_B;
        const char* sBh = sb + 2 * TILE_B;
        const char* sBl = sb + 3 * TILE_B;
#pragma unroll
        for (int kk = 0; kk < 2; kk++) {
            const int kc = kk * 16 + tq * 2;
            uint32_t ah[4][4], al[4][4];
#pragma unroll
            for (int mt = 0; mt < 4; mt++) {
                int ar = wm + mt * 16 + gid;
                ah[mt][0] = lds32(sAh, ar * PITCH + kc);
                ah[mt][1] = lds32(sAh, (ar + 8) * PITCH + kc);
                ah[mt][2] = lds32(sAh, ar * PITCH + kc + 8);
                ah[mt][3] = lds32(sAh, (ar + 8) * PITCH + kc + 8);
                al[mt][0] = lds32(sAl, ar * PITCH + kc);
                al[mt][1] = lds32(sAl, (ar + 8) * PITCH + kc);
                al[mt][2] = lds32(sAl, ar * PITCH + kc + 8);
                al[mt][3] = lds32(sAl, (ar + 8) * PITCH + kc + 8);
            }
            uint32_t bh[4][2], bl[4][2];
#pragma unroll
            for (int nt = 0; nt < 4; nt++) {
                int br = wn + nt * 8 + gid;
                bh[nt][0] = lds32(sBh, br * PITCH + kc);
                bh[nt][1] = lds32(sBh, br * PITCH + kc + 8);
                bl[nt][0] = lds32(sBl, br * PITCH + kc);
                bl[nt][1] = lds32(sBl, br * PITCH + kc + 8);
            }
#pragma unroll
            for (int mt = 0; mt < 4; mt++)
#pragma unroll
                for (int nt = 0; nt < 4; nt++) {
                    mma16816(acc[mt][nt], ah[mt], bh[nt]);
                    mma16816(acc[mt][nt], ah[mt], bl[nt]);
                    mma16816(acc[mt][nt], al[mt], bh[nt]);
                }
        }
    };

    // ---- 3-stage pipeline, one barrier per stage ---------------------------
    load_stage(0, 0); CP_COMMIT();
    load_stage(1, 1); CP_COMMIT();
    int buf = 0;
    for (int s = 0; s < S; s++) {
        if (s == S - 1) { CP_WAIT(0); } else { CP_WAIT(1); }
        __syncthreads();
        compute(buf);
        if (s + 2 < S) {
            int nb = buf + 2; if (nb >= 3) nb -= 3;
            load_stage(s + 2, nb); CP_COMMIT();
        }
        buf++; if (buf == 3) buf = 0;
    }

    // ---- epilogue -----------------------------------------------------------
#pragma unroll
    for (int mt = 0; mt < 4; mt++) {
        int row = m0 + wm + mt * 16 + gid;
#pragma unroll
        for (int nt = 0; nt < 4; nt++) {
            int col = n0 + wn + nt * 8 + tq * 2;
            float2 v0 = make_float2(acc[mt][nt][0], acc[mt][nt][1]);
            float2 v1 = make_float2(acc[mt][nt][2], acc[mt][nt][3]);
            *(float2*)&C[(size_t)row * Nc + col] = v0;
            *(float2*)&C[(size_t)(row + 8) * Nc + col] = v1;
        }
    }
}

// ---------------- fp32 -> bf16 hi/lo split ---------------------------------
__global__ void cvt_split_kernel(const float4* __restrict__ src,
                                 __nv_bfloat162* __restrict__ hi,
                                 __nv_bfloat162* __restrict__ lo, int n4)
{
    int i = blockIdx.x * blockDim.x + threadIdx.x;
    if (i >= n4) return;
    float4 v = src[i];
    __nv_bfloat16 h0 = __float2bfloat16(v.x);
    __nv_bfloat16 h1 = __float2bfloat16(v.y);
    __nv_bfloat16 h2 = __float2bfloat16(v.z);
    __nv_bfloat16 h3 = __float2bfloat16(v.w);
    __nv_bfloat16 l0 = __float2bfloat16(v.x - __bfloat162float(h0));
    __nv_bfloat16 l1 = __float2bfloat16(v.y - __bfloat162float(h1));
    __nv_bfloat16 l2 = __float2bfloat16(v.z - __bfloat162float(h2));
    __nv_bfloat16 l3 = __float2bfloat16(v.w - __bfloat162float(h3));
    hi[2 * i]     = __halves2bfloat162(h0, h1);
    hi[2 * i + 1] = __halves2bfloat162(h2, h3);
    lo[2 * i]     = __halves2bfloat162(l0, l1);
    lo[2 * i + 1] = __halves2bfloat162(l2, l3);
}

// ---------------- fp32 tiled GEMM (dt_proj, K=64) + softplus ----------------
template <int ACT>
__global__ __launch_bounds__(256, 2) void gemm128(
    const float* __restrict__ A, int lda,
    const float* __restrict__ W,
    const float* __restrict__ bias,
    float* __restrict__ C,
    int M, int N, int K)
{
    __shared__ float As[16][132];
    __shared__ float Ws[16][132];

    const int tid = threadIdx.x;
    const int m0 = blockIdx.y * 128;
    const int n0 = blockIdx.x * 128;
    const int tx = tid & 15;
    const int ty = tid >> 4;

    float acc[8][8];
#pragma unroll
    for (int i = 0; i < 8; i++)
#pragma unroll
        for (int j = 0; j < 8; j++) acc[i][j] = 0.f;

    const int r  = tid >> 2;
    const int c4 = (tid & 3) * 4;

    for (int k0 = 0; k0 < K; k0 += 16) {
#pragma unroll
        for (int p = 0; p < 2; p++) {
            int row = r + p * 64;
            float4 va = *(const float4*)&A[(size_t)(m0 + row) * lda + k0 + c4];
            As[c4 + 0][row] = va.x; As[c4 + 1][row] = va.y;
            As[c4 + 2][row] = va.z; As[c4 + 3][row] = va.w;
            float4 vw = *(const float4*)&W[(size_t)(n0 + row) * K + k0 + c4];
            Ws[c4 + 0][row] = vw.x; Ws[c4 + 1][row] = vw.y;
            Ws[c4 + 2][row] = vw.z; Ws[c4 + 3][row] = vw.w;
        }
        __syncthreads();

#pragma unroll
        for (int kk = 0; kk < 16; kk++) {
            float a[8], b[8];
#pragma unroll
            for (int i = 0; i < 8; i++) a[i] = As[kk][ty * 8 + i];
#pragma unroll
            for (int j = 0; j < 8; j++) b[j] = Ws[kk][tx * 8 + j];
#pragma unroll
            for (int i = 0; i < 8; i++)
#pragma unroll
                for (int j = 0; j < 8; j++) acc[i][j] = fmaf(a[i], b[j], acc[i][j]);
        }
        __syncthreads();
    }

#pragma unroll
    for (int i = 0; i < 8; i++) {
        int m = m0 + ty * 8 + i;
#pragma unroll
        for (int j = 0; j < 8; j++) {
            int n = n0 + tx * 8 + j;
            float v = acc[i][j];
            if (ACT == 1) {
                v += bias[n];
                v = (v > 20.f) ? v : log1pf(expf(v));
            }
            C[(size_t)m * N + n] = v;
        }
    }
}

// ---------------- skinny GEMM: C[M,96] = A[M,K] * W[96,K]^T -----------------
__global__ __launch_bounds__(256, 4) void gemm_skinny96(
    const float* __restrict__ A, int lda,
    const float* __restrict__ W,
    float* __restrict__ C, int M, int K)
{
    __shared__ float As[32][17];
    __shared__ float Ws[32][97];

    const int tid = threadIdx.x;
    const int m0 = blockIdx.x * 16;
    const int tx = tid & 31;
    const int ty = tid >> 5;

    float acc[2][3] = {{0.f, 0.f, 0.f}, {0.f, 0.f, 0.f}};

    for (int k0 = 0; k0 < K; k0 += 32) {
        if (tid < 128) {
            int rr = tid >> 3, cc = (tid & 7) * 4;
            float4 va = *(const float4*)&A[(size_t)(m0 + rr) * lda + k0 + cc];
            As[cc + 0][rr] = va.x; As[cc + 1][rr] = va.y;
            As[cc + 2][rr] = va.z; As[cc + 3][rr] = va.w;
        }
#pragma unroll
        for (int i = 0; i < 3; i++) {
            int idx = tid + i * 256;
            int rr = idx >> 3, cc = (idx & 7) * 4;
            float4 vw = *(const float4*)&W[(size_t)rr * K + k0 + cc];
            Ws[cc + 0][rr] = vw.x; Ws[cc + 1][rr] = vw.y;
            Ws[cc + 2][rr] = vw.z; Ws[cc + 3][rr] = vw.w;
        }
        __syncthreads();

#pragma unroll
        for (int kk = 0; kk < 32; kk++) {
            float a0 = As[kk][ty * 2 + 0];
            float a1 = As[kk][ty * 2 + 1];
            float b0 = Ws[kk][tx];
            float b1 = Ws[kk][tx + 32];
            float b2 = Ws[kk][tx + 64];
            acc[0][0] = fmaf(a0, b0, acc[0][0]);
            acc[0][1] = fmaf(a0, b1, acc[0][1]);
            acc[0][2] = fmaf(a0, b2, acc[0][2]);
            acc[1][0] = fmaf(a1, b0, acc[1][0]);
            acc[1][1] = fmaf(a1, b1, acc[1][1]);
            acc[1][2] = fmaf(a1, b2, acc[1][2]);
        }
        __syncthreads();
    }

#pragma unroll
    for (int i = 0; i < 2; i++) {
        int m = m0 + ty * 2 + i;
#pragma unroll
        for (int j = 0; j < 3; j++)
            C[(size_t)m * F_ + tx + j * 32] = acc[i][j];
    }
}

// ---------------- causal depthwise conv (K=4) + silu -----------------------
__global__ void conv_silu_kernel(const float* __restrict__ xz,
                                 const float* __restrict__ w,
                                 float* __restrict__ xc)
{
    int idx = blockIdx.x * blockDim.x + threadIdx.x;
    int e  = idx & (ED_ - 1);
    int bl = idx >> 11;
    int l  = bl & (L_ - 1);

    float acc = 0.f;
#pragma unroll
    for (int k = 0; k < 4; k++) {
        int ls = l - 3 + k;
        if (ls >= 0)
            acc = fmaf(w[e * 4 + k], xz[(size_t)(bl - 3 + k) * (2 * ED_) + e], acc);
    }
    xc[idx] = acc / (1.f + __expf(-acc));
}

// ============================================================================
// selective scan v2: smem-staged, coalesced, double-buffered cp.async.
// Block = 16 channels (one batch), 8 warps; warp = 2 channels x 16 states.
// Time chunked by 64 steps.
// ============================================================================
#define SCH 64

__global__ __launch_bounds__(256) void scan2_kernel(
    const float* __restrict__ xz,
    const float* __restrict__ xc,
    const float* __restrict__ dBC,
    const float* __restrict__ delta,
    const float* __restrict__ A_log,
    const float* __restrict__ Dp,
    __nv_bfloat16* __restrict__ yshi,
    __nv_bfloat16* __restrict__ yslo)
{
    __shared__ float sd[2][SCH][16];
    __shared__ float sx[2][SCH][16];
    __shared__ float sz[2][SCH][16];
    __shared__ float sbc[2][SCH][32];
    __shared__ float ysf[SCH][16];

    const int tid = threadIdx.x;
    const int e0  = blockIdx.x * 16;
    const int b   = blockIdx.y;
    const size_t rowBase = (size_t)b * L_;

    const int wid  = tid >> 5;
    const int lane = tid & 31;
    const int half = lane >> 4;
    const int n    = lane & 15;
    const int ch   = wid * 2 + half;
    const int e    = e0 + ch;

    const float a  = -expf(A_log[e * N_ + n]);
    const float dD = Dp[e];
    float h = 0.f;

    // loader indices
    const int lr = tid >> 2;          // 0..63
    const int lc = (tid & 3) * 4;     // 0,4,8,12

    auto load_chunk = [&](int chk, int buf) {
        size_t l0 = rowBase + (size_t)chk * SCH;
        cp_async16(smem_u32(&sd[buf][lr][lc]),
                   &delta[(l0 + lr) * ED_ + e0 + lc]);
        cp_async16(smem_u32(&sx[buf][lr][lc]),
                   &xc[(l0 + lr) * ED_ + e0 + lc]);
        cp_async16(smem_u32(&sz[buf][lr][lc]),
                   &xz[(l0 + lr) * (2 * ED_) + ED_ + e0 + lc]);
#pragma unroll
        for (int i = 0; i < 2; i++) {
            int idx = tid + i * 256;
            int r = idx >> 3, c = (idx & 7) * 4;
            cp_async16(smem_u32(&sbc[buf][r][c]),
                       &dBC[(l0 + r) * F_ + R_ + c]);
        }
    };

    load_chunk(0, 0); CP_COMMIT();
    load_chunk(1, 1); CP_COMMIT();

    const int NCHUNK = L_ / SCH;   // 16
    for (int chk = 0; chk < NCHUNK; chk++) {
        const int buf = chk & 1;
        if (chk == NCHUNK - 1) { CP_WAIT(0); } else { CP_WAIT(1); }
        __syncthreads();

#pragma unroll 4
        for (int l = 0; l < SCH; l++) {
            float dl  = sd[buf][l][ch];
            float xcv = sx[buf][l][ch];
            float Bv  = sbc[buf][l][n];
            float Cv  = sbc[buf][l][16 + n];
            float dA  = __expf(dl * a);
            h = fmaf(h, dA, dl * Bv * xcv);
            float p = h * Cv;
            p += __shfl_xor_sync(0xffffffffu, p, 1);
            p += __shfl_xor_sync(0xffffffffu, p, 2);
            p += __shfl_xor_sync(0xffffffffu, p, 4);
            p += __shfl_xor_sync(0xffffffffu, p, 8);
            if (n == 0) {
                float y  = p + dD * xcv;
                float zv = sz[buf][l][ch];
                float sv = zv / (1.f + __expf(-zv));
                ysf[l][ch] = y * sv;
            }
        }
        __syncthreads();   // ysf complete, buf fully consumed

        // coalesced ys hi/lo store: 128 threads, each 8 floats of one row
        if (tid < 128) {
            int r = tid >> 1, hs = (tid & 1) * 8;
            __nv_bfloat162 hi4[4], lo4[4];
#pragma unroll
            for (int j = 0; j < 4; j++) {
                float v0 = ysf[r][hs + 2 * j];
                float v1 = ysf[r][hs + 2 * j + 1];
                __nv_bfloat16 h0 = __float2bfloat16(v0);
                __nv_bfloat16 h1 = __float2bfloat16(v1);
                hi4[j] = __halves2bfloat162(h0, h1);
                lo4[j] = __halves2bfloat162(
                    __float2bfloat16(v0 - __bfloat162float(h0)),
                    __float2bfloat16(v1 - __bfloat162float(h1)));
            }
            size_t off = (rowBase + (size_t)chk * SCH + r) * ED_ + e0 + hs;
            *(uint4*)&yshi[off] = *(uint4*)hi4;
            *(uint4*)&yslo[off] = *(uint4*)lo4;
        }

        if (chk + 2 < NCHUNK) { load_chunk(chk + 2, buf); CP_COMMIT(); }
    }
}

// ---------------- launch ----------------------------------------------------
extern "C" void kernel_launch(void* const* d_in, const int* in_sizes, int n_in,
                              void* d_out, int out_size)
{
    const float* x         = (const float*)d_in[0];
    const float* in_proj_w = (const float*)d_in[1];
    const float* conv_w    = (const float*)d_in[2];
    const float* x_proj_w  = (const float*)d_in[3];
    const float* dt_proj_w = (const float*)d_in[4];
    const float* dt_proj_b = (const float*)d_in[5];
    const float* A_log     = (const float*)d_in[6];
    const float* Dp        = (const float*)d_in[7];
    const float* out_proj_w= (const float*)d_in[8];
    float* out = (float*)d_out;

    float *xz, *xc, *dBC, *delta;
    cudaGetSymbolAddress((void**)&xz,    g_xz);
    cudaGetSymbolAddress((void**)&xc,    g_xc);
    cudaGetSymbolAddress((void**)&dBC,   g_dBC);
    cudaGetSymbolAddress((void**)&delta, g_delta);

    __nv_bfloat16 *xhi, *xlo, *wihi, *wilo, *yshi, *yslo, *wohi, *wolo;
    cudaGetSymbolAddress((void**)&xhi,  g_xhi);
    cudaGetSymbolAddress((void**)&xlo,  g_xlo);
    cudaGetSymbolAddress((void**)&wihi, g_wihi);
    cudaGetSymbolAddress((void**)&wilo, g_wilo);
    cudaGetSymbolAddress((void**)&yshi, g_yshi);
    cudaGetSymbolAddress((void**)&yslo, g_yslo);
    cudaGetSymbolAddress((void**)&wohi, g_wohi);
    cudaGetSymbolAddress((void**)&wolo, g_wolo);

    static int smem_set = 0;
    if (!smem_set) {
        cudaFuncSetAttribute(gemm_mma_split,
                             cudaFuncAttributeMaxDynamicSharedMemorySize, GSM_TOTAL);
        smem_set = 1;
    }

    // 0) fp32 -> bf16 hi/lo splits
    cvt_split_kernel<<<(ML_ * DM_ / 4 + 255) / 256, 256>>>(
        (const float4*)x, (__nv_bfloat162*)xhi, (__nv_bfloat162*)xlo, ML_ * DM_ / 4);
    cvt_split_kernel<<<(2 * ED_ * DM_ / 4 + 255) / 256, 256>>>(
        (const float4*)in_proj_w, (__nv_bfloat162*)wihi, (__nv_bfloat162*)wilo,
        2 * ED_ * DM_ / 4);
    cvt_split_kernel<<<(DM_ * ED_ / 4 + 255) / 256, 256>>>(
        (const float4*)out_proj_w, (__nv_bfloat162*)wohi, (__nv_bfloat162*)wolo,
        DM_ * ED_ / 4);

    // 1) xz = x @ in_proj_w^T   [2048, 4096]   (mma.sync bf16-split)
    gemm_mma_split<<<dim3(2 * ED_ / 128, ML_ / 128), 256, GSM_TOTAL>>>(
        xhi, xlo, wihi, wilo, xz, 2 * ED_, DM_);

    // 2) xc = silu(causal depthwise conv(xz[:, :ED]))
    conv_silu_kernel<<<(ML_ * ED_) / 256, 256>>>(xz, conv_w, xc);

    // 3) dBC = xc @ x_proj_w^T   [2048, 96]
    gemm_skinny96<<<ML_ / 16, 256>>>(xc, ED_, x_proj_w, dBC, ML_, ED_);

    // 4) delta = softplus(dBC[:, :64] @ dt_proj_w^T + b)   [2048, 2048]
    gemm128<1><<<dim3(ED_ / 128, ML_ / 128), 256>>>(
        dBC, F_, dt_proj_w, dt_proj_b, delta, ML_, ED_, R_);

    // 5) selective scan -> ys hi/lo = (y * silu(z)) split   [smem-staged]
    scan2_kernel<<<dim3(ED_ / 16, B_), 256>>>(
        xz, xc, dBC, delta, A_log, Dp, yshi, yslo);

    // 6) out = ys @ out_proj_w^T  [2048, 1024]   (mma.sync bf16-split)
    gemm_mma_split<<<dim3(DM_ / 128, ML_ / 128), 256, GSM_TOTAL>>>(
        yshi, yslo, wohi, wolo, out, DM_, ED_);
}

// round 5
// speedup vs baseline: 2.7545x; 1.0157x over previous
#include <cuda_runtime.h>
#include <cuda_bf16.h>
#include <math.h>
#include <stdint.h>

// Problem constants
#define B_    2
#define L_    1024
#define DM_   1024
#define ED_   2048
#define N_    16
#define R_    64
#define K_    4
#define ML_   (B_ * L_)        // 2048 rows
#define F_    (R_ + 2 * N_)    // 96

// ---------------- scratch (device globals; no allocation allowed) ----------
__device__ float g_xz[ML_ * 2 * ED_];    // in_proj output  [2048, 4096]
__device__ float g_xc[ML_ * ED_];        // conv+silu       [2048, 2048]
__device__ float g_dBC[ML_ * F_];        // x_proj output   [2048, 96]
__device__ float g_delta[ML_ * ED_];     // softplus(dt_proj) [2048, 2048]

// bf16 hi/lo split scratch (16B-aligned for cp.async / vector access)
__device__ __align__(16) __nv_bfloat16 g_xhi[ML_ * DM_];
__device__ __align__(16) __nv_bfloat16 g_xlo[ML_ * DM_];
__device__ __align__(16) __nv_bfloat16 g_wihi[2 * ED_ * DM_];
__device__ __align__(16) __nv_bfloat16 g_wilo[2 * ED_ * DM_];
__device__ __align__(16) __nv_bfloat16 g_yshi[ML_ * ED_];
__device__ __align__(16) __nv_bfloat16 g_yslo[ML_ * ED_];
__device__ __align__(16) __nv_bfloat16 g_wohi[DM_ * ED_];
__device__ __align__(16) __nv_bfloat16 g_wolo[DM_ * ED_];

// ============================================================================
// helpers
// ============================================================================
__device__ __forceinline__ uint32_t smem_u32(const void* p) {
    uint32_t a;
    asm("{ .reg .u64 t; cvta.to.shared.u64 t, %1; cvt.u32.u64 %0, t; }"
        : "=r"(a) : "l"(p));
    return a;
}

__device__ __forceinline__ void cp_async16(uint32_t saddr, const void* gaddr) {
    asm volatile("cp.async.cg.shared.global [%0], [%1], 16;"
                 :: "r"(saddr), "l"(gaddr));
}
#define CP_COMMIT() asm volatile("cp.async.commit_group;" ::: "memory")
#define CP_WAIT(n)  asm volatile("cp.async.wait_group %0;" :: "n"(n) : "memory")

__device__ __forceinline__ void mma16816(float* d, const uint32_t* a,
                                         const uint32_t* b) {
    asm volatile(
        "mma.sync.aligned.m16n8k16.row.col.f32.bf16.bf16.f32 "
        "{%0,%1,%2,%3}, {%4,%5,%6,%7}, {%8,%9}, {%0,%1,%2,%3};"
        : "+f"(d[0]), "+f"(d[1]), "+f"(d[2]), "+f"(d[3])
        : "r"(a[0]), "r"(a[1]), "r"(a[2]), "r"(a[3]),
          "r"(b[0]), "r"(b[1]));
}

__device__ __forceinline__ void ldsm4(uint32_t* r, uint32_t addr) {
    asm volatile("ldmatrix.sync.aligned.m8n8.x4.shared.b16 {%0,%1,%2,%3}, [%4];"
                 : "=r"(r[0]), "=r"(r[1]), "=r"(r[2]), "=r"(r[3])
                 : "r"(addr));
}

// ============================================================================
// bf16-split mma.sync GEMM: C[M,N] = Ahi/lo[M,K] * (Bhi/lo[N,K])^T  (fp32 acc)
// CTA tile 128x128, K staged by 32; 8 warps (2 M x 4 N), warp tile 64x32.
// ldmatrix fragment loads; 2-stage cp.async pipeline; 2 CTAs/SM.
// ============================================================================
#define PITCH 40
#define TILE_B (128 * PITCH * 2)          // 10240 B per operand tile
#define STAGE_B (4 * TILE_B)              // 40960 B per K-stage
#define GSM_TOTAL (2 * STAGE_B)           // 81920 B

__global__ __launch_bounds__(256, 2) void gemm_mma_split(
    const __nv_bfloat16* __restrict__ Ahi, const __nv_bfloat16* __restrict__ Alo,
    const __nv_bfloat16* __restrict__ Bhi, const __nv_bfloat16* __restrict__ Blo,
    float* __restrict__ C, int Nc, int K)
{
    extern __shared__ char smem[];
    const uint32_t sbase = smem_u32(smem);

    const int tid  = threadIdx.x;
    const int wid  = tid >> 5;
    const int lane = tid & 31;
    const int gid  = lane >> 2;      // 0..7
    const int tq   = lane & 3;       // 0..3
    const int wm   = (wid >> 2) * 64;    // warp M offset (0/64)
    const int wn   = (wid & 3) * 32;     // warp N offset (0/32/64/96)
    const int m0 = blockIdx.y * 128;
    const int n0 = blockIdx.x * 128;

    // ldmatrix per-thread selectors
    const int t7  = lane & 7;
    const int grp = lane >> 3;            // 0..3
    const int aRow = (grp & 1) * 8 + t7;  // A: row sel by grp bit0
    const int aCol = (grp >> 1) * 8;      // A: col sel by grp bit1
    const int bRow = (grp >> 1) * 8 + t7; // B: row sel by grp bit1
    const int bCol = (grp & 1) * 8;       // B: col sel by grp bit0

    const __nv_bfloat16* srcs[4] = {
        Ahi + (size_t)m0 * K, Alo + (size_t)m0 * K,
        Bhi + (size_t)n0 * K, Blo + (size_t)n0 * K };

    const int S = K / 32;

    float acc[4][4][4];
#pragma unroll
    for (int i = 0; i < 4; i++)
#pragma unroll
        for (int j = 0; j < 4; j++)
#pragma unroll
            for (int r = 0; r < 4; r++) acc[i][j][r] = 0.f;

    const int lrow = tid >> 2;        // 0..63
    const int lc   = tid & 3;         // 16B chunk 0..3
    auto load_stage = [&](int s, int buf) {
        const int k0 = s * 32;
        char* sb = smem + buf * STAGE_B;
#pragma unroll
        for (int t = 0; t < 4; t++) {
            const __nv_bfloat16* src = srcs[t] + k0 + lc * 8;
            char* tb = sb + t * TILE_B;
#pragma unroll
            for (int i = 0; i < 2; i++) {
                int r = lrow + i * 64;
                cp_async16(smem_u32(tb + r * (PITCH * 2) + lc * 16),
                           src + (size_t)r * K);
            }
        }
    };

    auto compute = [&](int buf) {
        const uint32_t sb  = sbase + buf * STAGE_B;
        const uint32_t sAh = sb;                       // + TILE_B -> Alo
        const uint32_t sBh = sb + 2 * TILE_B;          // + TILE_B -> Blo
#pragma unroll
        for (int kk = 0; kk < 2; kk++) {
            const uint32_t kc = kk * 16;
            // B fragments: [pair p][4 regs] = {b[nt0].lo, b[nt0].hi, b[nt1].lo, b[nt1].hi}
            uint32_t bh[2][4], bl[2][4];
#pragma unroll
            for (int p = 0; p < 2; p++) {
                uint32_t baddr = sBh +
                    ((wn + p * 16 + bRow) * PITCH + kc + bCol) * 2;
                ldsm4(bh[p], baddr);
                ldsm4(bl[p], baddr + TILE_B);
            }
#pragma unroll
            for (int mt = 0; mt < 4; mt++) {
                uint32_t aaddr = sAh +
                    ((wm + mt * 16 + aRow) * PITCH + kc + aCol) * 2;
                uint32_t ah[4], al[4];
                ldsm4(ah, aaddr);
                ldsm4(al, aaddr + TILE_B);
#pragma unroll
                for (int nt = 0; nt < 4; nt++) {
                    const uint32_t* bbh = &bh[nt >> 1][(nt & 1) * 2];
                    const uint32_t* bbl = &bl[nt >> 1][(nt & 1) * 2];
                    mma16816(acc[mt][nt], ah, bbh);
                    mma16816(acc[mt][nt], ah, bbl);
                    mma16816(acc[mt][nt], al, bbh);
                }
            }
        }
    };

    // ---- 2-stage pipeline ----------------------------------------------------
    load_stage(0, 0); CP_COMMIT();
    load_stage(1, 1); CP_COMMIT();
    for (int s = 0; s < S; s++) {
        if (s == S - 1) { CP_WAIT(0); } else { CP_WAIT(1); }
        __syncthreads();
        compute(s & 1);
        __syncthreads();
        if (s + 2 < S) { load_stage(s + 2, s & 1); CP_COMMIT(); }
    }

    // ---- epilogue -----------------------------------------------------------
#pragma unroll
    for (int mt = 0; mt < 4; mt++) {
        int row = m0 + wm + mt * 16 + gid;
#pragma unroll
        for (int nt = 0; nt < 4; nt++) {
            int col = n0 + wn + nt * 8 + tq * 2;
            float2 v0 = make_float2(acc[mt][nt][0], acc[mt][nt][1]);
            float2 v1 = make_float2(acc[mt][nt][2], acc[mt][nt][3]);
            *(float2*)&C[(size_t)row * Nc + col] = v0;
            *(float2*)&C[(size_t)(row + 8) * Nc + col] = v1;
        }
    }
}

// ---------------- fp32 -> bf16 hi/lo split (3 tensors fused) ----------------
__device__ __forceinline__ void split4(const float4* src, __nv_bfloat162* hi,
                                       __nv_bfloat162* lo, int i)
{
    float4 v = src[i];
    __nv_bfloat16 h0 = __float2bfloat16(v.x);
    __nv_bfloat16 h1 = __float2bfloat16(v.y);
    __nv_bfloat16 h2 = __float2bfloat16(v.z);
    __nv_bfloat16 h3 = __float2bfloat16(v.w);
    hi[2 * i]     = __halves2bfloat162(h0, h1);
    hi[2 * i + 1] = __halves2bfloat162(h2, h3);
    lo[2 * i]     = __halves2bfloat162(
        __float2bfloat16(v.x - __bfloat162float(h0)),
        __float2bfloat16(v.y - __bfloat162float(h1)));
    lo[2 * i + 1] = __halves2bfloat162(
        __float2bfloat16(v.z - __bfloat162float(h2)),
        __float2bfloat16(v.w - __bfloat162float(h3)));
}

__global__ void cvt_split3_kernel(
    const float4* s1, __nv_bfloat162* h1, __nv_bfloat162* l1, int n1,
    const float4* s2, __nv_bfloat162* h2, __nv_bfloat162* l2, int n2,
    const float4* s3, __nv_bfloat162* h3, __nv_bfloat162* l3, int n3)
{
    int i = blockIdx.x * blockDim.x + threadIdx.x;
    if (i < n1) { split4(s1, h1, l1, i); return; }
    i -= n1;
    if (i < n2) { split4(s2, h2, l2, i); return; }
    i -= n2;
    if (i < n3) { split4(s3, h3, l3, i); }
}

// ---------------- fp32 tiled GEMM (dt_proj, K=64) + softplus ----------------
template <int ACT>
__global__ __launch_bounds__(256, 2) void gemm128(
    const float* __restrict__ A, int lda,
    const float* __restrict__ W,
    const float* __restrict__ bias,
    float* __restrict__ C,
    int M, int N, int K)
{
    __shared__ float As[16][132];
    __shared__ float Ws[16][132];

    const int tid = threadIdx.x;
    const int m0 = blockIdx.y * 128;
    const int n0 = blockIdx.x * 128;
    const int tx = tid & 15;
    const int ty = tid >> 4;

    float acc[8][8];
#pragma unroll
    for (int i = 0; i < 8; i++)
#pragma unroll
        for (int j = 0; j < 8; j++) acc[i][j] = 0.f;

    const int r  = tid >> 2;
    const int c4 = (tid & 3) * 4;

    for (int k0 = 0; k0 < K; k0 += 16) {
#pragma unroll
        for (int p = 0; p < 2; p++) {
            int row = r + p * 64;
            float4 va = *(const float4*)&A[(size_t)(m0 + row) * lda + k0 + c4];
            As[c4 + 0][row] = va.x; As[c4 + 1][row] = va.y;
            As[c4 + 2][row] = va.z; As[c4 + 3][row] = va.w;
            float4 vw = *(const float4*)&W[(size_t)(n0 + row) * K + k0 + c4];
            Ws[c4 + 0][row] = vw.x; Ws[c4 + 1][row] = vw.y;
            Ws[c4 + 2][row] = vw.z; Ws[c4 + 3][row] = vw.w;
        }
        __syncthreads();

#pragma unroll
        for (int kk = 0; kk < 16; kk++) {
            float a[8], b[8];
#pragma unroll
            for (int i = 0; i < 8; i++) a[i] = As[kk][ty * 8 + i];
#pragma unroll
            for (int j = 0; j < 8; j++) b[j] = Ws[kk][tx * 8 + j];
#pragma unroll
            for (int i = 0; i < 8; i++)
#pragma unroll
                for (int j = 0; j < 8; j++) acc[i][j] = fmaf(a[i], b[j], acc[i][j]);
        }
        __syncthreads();
    }

#pragma unroll
    for (int i = 0; i < 8; i++) {
        int m = m0 + ty * 8 + i;
#pragma unroll
        for (int j = 0; j < 8; j++) {
            int n = n0 + tx * 8 + j;
            float v = acc[i][j];
            if (ACT == 1) {
                v += bias[n];
                v = (v > 20.f) ? v : log1pf(expf(v));
            }
            C[(size_t)m * N + n] = v;
        }
    }
}

// ---------------- skinny GEMM: C[M,96] = A[M,K] * W[96,K]^T -----------------
__global__ __launch_bounds__(256, 4) void gemm_skinny96(
    const float* __restrict__ A, int lda,
    const float* __restrict__ W,
    float* __restrict__ C, int M, int K)
{
    __shared__ float As[32][17];
    __shared__ float Ws[32][97];

    const int tid = threadIdx.x;
    const int m0 = blockIdx.x * 16;
    const int tx = tid & 31;
    const int ty = tid >> 5;

    float acc[2][3] = {{0.f, 0.f, 0.f}, {0.f, 0.f, 0.f}};

    for (int k0 = 0; k0 < K; k0 += 32) {
        if (tid < 128) {
            int rr = tid >> 3, cc = (tid & 7) * 4;
            float4 va = *(const float4*)&A[(size_t)(m0 + rr) * lda + k0 + cc];
            As[cc + 0][rr] = va.x; As[cc + 1][rr] = va.y;
            As[cc + 2][rr] = va.z; As[cc + 3][rr] = va.w;
        }
#pragma unroll
        for (int i = 0; i < 3; i++) {
            int idx = tid + i * 256;
            int rr = idx >> 3, cc = (idx & 7) * 4;
            float4 vw = *(const float4*)&W[(size_t)rr * K + k0 + cc];
            Ws[cc + 0][rr] = vw.x; Ws[cc + 1][rr] = vw.y;
            Ws[cc + 2][rr] = vw.z; Ws[cc + 3][rr] = vw.w;
        }
        __syncthreads();

#pragma unroll
        for (int kk = 0; kk < 32; kk++) {
            float a0 = As[kk][ty * 2 + 0];
            float a1 = As[kk][ty * 2 + 1];
            float b0 = Ws[kk][tx];
            float b1 = Ws[kk][tx + 32];
            float b2 = Ws[kk][tx + 64];
            acc[0][0] = fmaf(a0, b0, acc[0][0]);
            acc[0][1] = fmaf(a0, b1, acc[0][1]);
            acc[0][2] = fmaf(a0, b2, acc[0][2]);
            acc[1][0] = fmaf(a1, b0, acc[1][0]);
            acc[1][1] = fmaf(a1, b1, acc[1][1]);
            acc[1][2] = fmaf(a1, b2, acc[1][2]);
        }
        __syncthreads();
    }

#pragma unroll
    for (int i = 0; i < 2; i++) {
        int m = m0 + ty * 2 + i;
#pragma unroll
        for (int j = 0; j < 3; j++)
            C[(size_t)m * F_ + tx + j * 32] = acc[i][j];
    }
}

// ---------------- causal depthwise conv (K=4) + silu -----------------------
__global__ void conv_silu_kernel(const float* __restrict__ xz,
                                 const float* __restrict__ w,
                                 float* __restrict__ xc)
{
    int idx = blockIdx.x * blockDim.x + threadIdx.x;
    int e  = idx & (ED_ - 1);
    int bl = idx >> 11;
    int l  = bl & (L_ - 1);

    float acc = 0.f;
#pragma unroll
    for (int k = 0; k < 4; k++) {
        int ls = l - 3 + k;
        if (ls >= 0)
            acc = fmaf(w[e * 4 + k], xz[(size_t)(bl - 3 + k) * (2 * ED_) + e], acc);
    }
    xc[idx] = acc / (1.f + __expf(-acc));
}

// ============================================================================
// selective scan: smem-staged, coalesced, double-buffered cp.async.
// ============================================================================
#define SCH 64

__global__ __launch_bounds__(256) void scan2_kernel(
    const float* __restrict__ xz,
    const float* __restrict__ xc,
    const float* __restrict__ dBC,
    const float* __restrict__ delta,
    const float* __restrict__ A_log,
    const float* __restrict__ Dp,
    __nv_bfloat16* __restrict__ yshi,
    __nv_bfloat16* __restrict__ yslo)
{
    __shared__ float sd[2][SCH][16];
    __shared__ float sx[2][SCH][16];
    __shared__ float sz[2][SCH][16];
    __shared__ float sbc[2][SCH][32];
    __shared__ float ysf[SCH][16];

    const int tid = threadIdx.x;
    const int e0  = blockIdx.x * 16;
    const int b   = blockIdx.y;
    const size_t rowBase = (size_t)b * L_;

    const int wid  = tid >> 5;
    const int lane = tid & 31;
    const int half = lane >> 4;
    const int n    = lane & 15;
    const int ch   = wid * 2 + half;
    const int e    = e0 + ch;

    const float a  = -expf(A_log[e * N_ + n]);
    const float dD = Dp[e];
    float h = 0.f;

    const int lr = tid >> 2;
    const int lc = (tid & 3) * 4;

    auto load_chunk = [&](int chk, int buf) {
        size_t l0 = rowBase + (size_t)chk * SCH;
        cp_async16(smem_u32(&sd[buf][lr][lc]),
                   &delta[(l0 + lr) * ED_ + e0 + lc]);
        cp_async16(smem_u32(&sx[buf][lr][lc]),
                   &xc[(l0 + lr) * ED_ + e0 + lc]);
        cp_async16(smem_u32(&sz[buf][lr][lc]),
                   &xz[(l0 + lr) * (2 * ED_) + ED_ + e0 + lc]);
#pragma unroll
        for (int i = 0; i < 2; i++) {
            int idx = tid + i * 256;
            int r = idx >> 3, c = (idx & 7) * 4;
            cp_async16(smem_u32(&sbc[buf][r][c]),
                       &dBC[(l0 + r) * F_ + R_ + c]);
        }
    };

    load_chunk(0, 0); CP_COMMIT();
    load_chunk(1, 1); CP_COMMIT();

    const int NCHUNK = L_ / SCH;   // 16
    for (int chk = 0; chk < NCHUNK; chk++) {
        const int buf = chk & 1;
        if (chk == NCHUNK - 1) { CP_WAIT(0); } else { CP_WAIT(1); }
        __syncthreads();

#pragma unroll 4
        for (int l = 0; l < SCH; l++) {
            float dl  = sd[buf][l][ch];
            float xcv = sx[buf][l][ch];
            float Bv  = sbc[buf][l][n];
            float Cv  = sbc[buf][l][16 + n];
            float dA  = __expf(dl * a);
            h = fmaf(h, dA, dl * Bv * xcv);
            float p = h * Cv;
            p += __shfl_xor_sync(0xffffffffu, p, 1);
            p += __shfl_xor_sync(0xffffffffu, p, 2);
            p += __shfl_xor_sync(0xffffffffu, p, 4);
            p += __shfl_xor_sync(0xffffffffu, p, 8);
            if (n == 0) {
                float y  = p + dD * xcv;
                float zv = sz[buf][l][ch];
                float sv = zv / (1.f + __expf(-zv));
                ysf[l][ch] = y * sv;
            }
        }
        __syncthreads();

        if (tid < 128) {
            int r = tid >> 1, hs = (tid & 1) * 8;
            __nv_bfloat162 hi4[4], lo4[4];
#pragma unroll
            for (int j = 0; j < 4; j++) {
                float v0 = ysf[r][hs + 2 * j];
                float v1 = ysf[r][hs + 2 * j + 1];
                __nv_bfloat16 h0 = __float2bfloat16(v0);
                __nv_bfloat16 h1 = __float2bfloat16(v1);
                hi4[j] = __halves2bfloat162(h0, h1);
                lo4[j] = __halves2bfloat162(
                    __float2bfloat16(v0 - __bfloat162float(h0)),
                    __float2bfloat16(v1 - __bfloat162float(h1)));
            }
            size_t off = (rowBase + (size_t)chk * SCH + r) * ED_ + e0 + hs;
            *(uint4*)&yshi[off] = *(uint4*)hi4;
            *(uint4*)&yslo[off] = *(uint4*)lo4;
        }

        if (chk + 2 < NCHUNK) { load_chunk(chk + 2, buf); CP_COMMIT(); }
    }
}

// ---------------- launch ----------------------------------------------------
extern "C" void kernel_launch(void* const* d_in, const int* in_sizes, int n_in,
                              void* d_out, int out_size)
{
    const float* x         = (const float*)d_in[0];
    const float* in_proj_w = (const float*)d_in[1];
    const float* conv_w    = (const float*)d_in[2];
    const float* x_proj_w  = (const float*)d_in[3];
    const float* dt_proj_w = (const float*)d_in[4];
    const float* dt_proj_b = (const float*)d_in[5];
    const float* A_log     = (const float*)d_in[6];
    const float* Dp        = (const float*)d_in[7];
    const float* out_proj_w= (const float*)d_in[8];
    float* out = (float*)d_out;

    float *xz, *xc, *dBC, *delta;
    cudaGetSymbolAddress((void**)&xz,    g_xz);
    cudaGetSymbolAddress((void**)&xc,    g_xc);
    cudaGetSymbolAddress((void**)&dBC,   g_dBC);
    cudaGetSymbolAddress((void**)&delta, g_delta);

    __nv_bfloat16 *xhi, *xlo, *wihi, *wilo, *yshi, *yslo, *wohi, *wolo;
    cudaGetSymbolAddress((void**)&xhi,  g_xhi);
    cudaGetSymbolAddress((void**)&xlo,  g_xlo);
    cudaGetSymbolAddress((void**)&wihi, g_wihi);
    cudaGetSymbolAddress((void**)&wilo, g_wilo);
    cudaGetSymbolAddress((void**)&yshi, g_yshi);
    cudaGetSymbolAddress((void**)&yslo, g_yslo);
    cudaGetSymbolAddress((void**)&wohi, g_wohi);
    cudaGetSymbolAddress((void**)&wolo, g_wolo);

    static int smem_set = 0;
    if (!smem_set) {
        cudaFuncSetAttribute(gemm_mma_split,
                             cudaFuncAttributeMaxDynamicSharedMemorySize, GSM_TOTAL);
        smem_set = 1;
    }

    // 0) fp32 -> bf16 hi/lo splits (x, in_proj_w, out_proj_w fused)
    {
        int n1 = ML_ * DM_ / 4;
        int n2 = 2 * ED_ * DM_ / 4;
        int n3 = DM_ * ED_ / 4;
        cvt_split3_kernel<<<(n1 + n2 + n3 + 255) / 256, 256>>>(
            (const float4*)x, (__nv_bfloat162*)xhi, (__nv_bfloat162*)xlo, n1,
            (const float4*)in_proj_w, (__nv_bfloat162*)wihi, (__nv_bfloat162*)wilo, n2,
            (const float4*)out_proj_w, (__nv_bfloat162*)wohi, (__nv_bfloat162*)wolo, n3);
    }

    // 1) xz = x @ in_proj_w^T   [2048, 4096]   (mma.sync bf16-split)
    gemm_mma_split<<<dim3(2 * ED_ / 128, ML_ / 128), 256, GSM_TOTAL>>>(
        xhi, xlo, wihi, wilo, xz, 2 * ED_, DM_);

    // 2) xc = silu(causal depthwise conv(xz[:, :ED]))
    conv_silu_kernel<<<(ML_ * ED_) / 256, 256>>>(xz, conv_w, xc);

    // 3) dBC = xc @ x_proj_w^T   [2048, 96]
    gemm_skinny96<<<ML_ / 16, 256>>>(xc, ED_, x_proj_w, dBC, ML_, ED_);

    // 4) delta = softplus(dBC[:, :64] @ dt_proj_w^T + b)   [2048, 2048]
    gemm128<1><<<dim3(ED_ / 128, ML_ / 128), 256>>>(
        dBC, F_, dt_proj_w, dt_proj_b, delta, ML_, ED_, R_);

    // 5) selective scan -> ys hi/lo = (y * silu(z)) split   [smem-staged]
    scan2_kernel<<<dim3(ED_ / 16, B_), 256>>>(
        xz, xc, dBC, delta, A_log, Dp, yshi, yslo);

    // 6) out = ys @ out_proj_w^T  [2048, 1024]   (mma.sync bf16-split)
    gemm_mma_split<<<dim3(DM_ / 128, ML_ / 128), 256, GSM_TOTAL>>>(
        yshi, yslo, wohi, wolo, out, DM_, ED_);
}

// round 6
// speedup vs baseline: 3.1406x; 1.1401x over previous
#include <cuda_runtime.h>
#include <cuda_bf16.h>
#include <math.h>
#include <stdint.h>

// Problem constants
#define B_    2
#define L_    1024
#define DM_   1024
#define ED_   2048
#define N_    16
#define R_    64
#define K_    4
#define ML_   (B_ * L_)        // 2048 rows
#define F_    96               // x_proj out cols (valid)
#define FP_   128              // padded
#define KSPLIT 4

// ---------------- scratch (device globals; no allocation allowed) ----------
__device__ float g_xz[ML_ * 2 * ED_];      // in_proj output  [2048, 4096]
__device__ float g_xc[ML_ * ED_];          // conv+silu fp32  [2048, 2048]
__device__ float g_delta[ML_ * ED_];       // softplus(dt_proj)
__device__ float g_dBCpart[KSPLIT * ML_ * FP_];  // split-K partials
__device__ float g_dBCr[ML_ * FP_];        // reduced dBC (padded lda 128)

// bf16 hi/lo split scratch (16B-aligned)
__device__ __align__(16) __nv_bfloat16 g_xhi[ML_ * DM_];
__device__ __align__(16) __nv_bfloat16 g_xlo[ML_ * DM_];
__device__ __align__(16) __nv_bfloat16 g_wihi[2 * ED_ * DM_];
__device__ __align__(16) __nv_bfloat16 g_wilo[2 * ED_ * DM_];
__device__ __align__(16) __nv_bfloat16 g_yshi[ML_ * ED_];
__device__ __align__(16) __nv_bfloat16 g_yslo[ML_ * ED_];
__device__ __align__(16) __nv_bfloat16 g_wohi[DM_ * ED_];
__device__ __align__(16) __nv_bfloat16 g_wolo[DM_ * ED_];
__device__ __align__(16) __nv_bfloat16 g_xchi[ML_ * ED_];
__device__ __align__(16) __nv_bfloat16 g_xclo[ML_ * ED_];
__device__ __align__(16) __nv_bfloat16 g_wphi[FP_ * ED_];   // rows 96..127 stay 0
__device__ __align__(16) __nv_bfloat16 g_wplo[FP_ * ED_];
__device__ __align__(16) __nv_bfloat16 g_dthi[ML_ * R_];
__device__ __align__(16) __nv_bfloat16 g_dtlo[ML_ * R_];
__device__ __align__(16) __nv_bfloat16 g_dtwhi[ED_ * R_];
__device__ __align__(16) __nv_bfloat16 g_dtwlo[ED_ * R_];

// ============================================================================
// helpers
// ============================================================================
__device__ __forceinline__ uint32_t smem_u32(const void* p) {
    uint32_t a;
    asm("{ .reg .u64 t; cvta.to.shared.u64 t, %1; cvt.u32.u64 %0, t; }"
        : "=r"(a) : "l"(p));
    return a;
}

__device__ __forceinline__ void cp_async16(uint32_t saddr, const void* gaddr) {
    asm volatile("cp.async.cg.shared.global [%0], [%1], 16;"
                 :: "r"(saddr), "l"(gaddr));
}
#define CP_COMMIT() asm volatile("cp.async.commit_group;" ::: "memory")
#define CP_WAIT(n)  asm volatile("cp.async.wait_group %0;" :: "n"(n) : "memory")

__device__ __forceinline__ void mma16816(float* d, const uint32_t* a,
                                         const uint32_t* b) {
    asm volatile(
        "mma.sync.aligned.m16n8k16.row.col.f32.bf16.bf16.f32 "
        "{%0,%1,%2,%3}, {%4,%5,%6,%7}, {%8,%9}, {%0,%1,%2,%3};"
        : "+f"(d[0]), "+f"(d[1]), "+f"(d[2]), "+f"(d[3])
        : "r"(a[0]), "r"(a[1]), "r"(a[2]), "r"(a[3]),
          "r"(b[0]), "r"(b[1]));
}

__device__ __forceinline__ void ldsm4(uint32_t* r, uint32_t addr) {
    asm volatile("ldmatrix.sync.aligned.m8n8.x4.shared.b16 {%0,%1,%2,%3}, [%4];"
                 : "=r"(r[0]), "=r"(r[1]), "=r"(r[2]), "=r"(r[3])
                 : "r"(addr));
}

// ============================================================================
// bf16-split mma.sync GEMM (universal):
//   C[z][M,N] += Ahi/lo[M, kbase:kbase+Ksub] * (Bhi/lo[N, ...])^T
// CTA tile 128x128, K staged by 32; 8 warps (2Mx4N), warp tile 64x32.
// grid.z slices K (deterministic partial buffers). ACT=1: softplus(v+bias).
// ============================================================================
#define PITCH 40
#define TILE_B (128 * PITCH * 2)
#define STAGE_B (4 * TILE_B)
#define GSM_TOTAL (2 * STAGE_B)           // 81920 B

template <int ACT>
__global__ __launch_bounds__(256, 2) void gemm_mma_split(
    const __nv_bfloat16* __restrict__ Ahi, const __nv_bfloat16* __restrict__ Alo,
    const __nv_bfloat16* __restrict__ Bhi, const __nv_bfloat16* __restrict__ Blo,
    float* __restrict__ C, int Nc, int Ksub, int Kfull,
    const float* __restrict__ bias, size_t partStride)
{
    extern __shared__ char smem[];
    const uint32_t sbase = smem_u32(smem);

    const int tid  = threadIdx.x;
    const int wid  = tid >> 5;
    const int lane = tid & 31;
    const int gid  = lane >> 2;
    const int tq   = lane & 3;
    const int wm   = (wid >> 2) * 64;
    const int wn   = (wid & 3) * 32;
    const int m0 = blockIdx.y * 128;
    const int n0 = blockIdx.x * 128;
    const int kbase = blockIdx.z * Ksub;

    const int t7  = lane & 7;
    const int grp = lane >> 3;
    const int aRow = (grp & 1) * 8 + t7;
    const int aCol = (grp >> 1) * 8;
    const int bRow = (grp >> 1) * 8 + t7;
    const int bCol = (grp & 1) * 8;

    const __nv_bfloat16* srcs[4] = {
        Ahi + (size_t)m0 * Kfull + kbase, Alo + (size_t)m0 * Kfull + kbase,
        Bhi + (size_t)n0 * Kfull + kbase, Blo + (size_t)n0 * Kfull + kbase };

    C += (size_t)blockIdx.z * partStride;

    const int S = Ksub / 32;

    float acc[4][4][4];
#pragma unroll
    for (int i = 0; i < 4; i++)
#pragma unroll
        for (int j = 0; j < 4; j++)
#pragma unroll
            for (int r = 0; r < 4; r++) acc[i][j][r] = 0.f;

    const int lrow = tid >> 2;
    const int lc   = tid & 3;
    auto load_stage = [&](int s, int buf) {
        const int k0 = s * 32;
        char* sb = smem + buf * STAGE_B;
#pragma unroll
        for (int t = 0; t < 4; t++) {
            const __nv_bfloat16* src = srcs[t] + k0 + lc * 8;
            char* tb = sb + t * TILE_B;
#pragma unroll
            for (int i = 0; i < 2; i++) {
                int r = lrow + i * 64;
                cp_async16(smem_u32(tb + r * (PITCH * 2) + lc * 16),
                           src + (size_t)r * Kfull);
            }
        }
    };

    auto compute = [&](int buf) {
        const uint32_t sb  = sbase + buf * STAGE_B;
        const uint32_t sAh = sb;
        const uint32_t sBh = sb + 2 * TILE_B;
#pragma unroll
        for (int kk = 0; kk < 2; kk++) {
            const uint32_t kc = kk * 16;
            uint32_t bh[2][4], bl[2][4];
#pragma unroll
            for (int p = 0; p < 2; p++) {
                uint32_t baddr = sBh +
                    ((wn + p * 16 + bRow) * PITCH + kc + bCol) * 2;
                ldsm4(bh[p], baddr);
                ldsm4(bl[p], baddr + TILE_B);
            }
#pragma unroll
            for (int mt = 0; mt < 4; mt++) {
                uint32_t aaddr = sAh +
                    ((wm + mt * 16 + aRow) * PITCH + kc + aCol) * 2;
                uint32_t ah[4], al[4];
                ldsm4(ah, aaddr);
                ldsm4(al, aaddr + TILE_B);
#pragma unroll
                for (int nt = 0; nt < 4; nt++) {
                    const uint32_t* bbh = &bh[nt >> 1][(nt & 1) * 2];
                    const uint32_t* bbl = &bl[nt >> 1][(nt & 1) * 2];
                    mma16816(acc[mt][nt], ah, bbh);
                    mma16816(acc[mt][nt], ah, bbl);
                    mma16816(acc[mt][nt], al, bbh);
                }
            }
        }
    };

    load_stage(0, 0); CP_COMMIT();
    load_stage(1, 1); CP_COMMIT();
    for (int s = 0; s < S; s++) {
        if (s == S - 1) { CP_WAIT(0); } else { CP_WAIT(1); }
        __syncthreads();
        compute(s & 1);
        __syncthreads();
        if (s + 2 < S) { load_stage(s + 2, s & 1); CP_COMMIT(); }
    }

#pragma unroll
    for (int mt = 0; mt < 4; mt++) {
        int row = m0 + wm + mt * 16 + gid;
#pragma unroll
        for (int nt = 0; nt < 4; nt++) {
            int col = n0 + wn + nt * 8 + tq * 2;
            float v[4] = {acc[mt][nt][0], acc[mt][nt][1],
                          acc[mt][nt][2], acc[mt][nt][3]};
            if (ACT == 1) {
                float b0 = bias[col], b1 = bias[col + 1];
                v[0] += b0; v[1] += b1; v[2] += b0; v[3] += b1;
#pragma unroll
                for (int r = 0; r < 4; r++)
                    v[r] = (v[r] > 20.f) ? v[r] : log1pf(expf(v[r]));
            }
            *(float2*)&C[(size_t)row * Nc + col] = make_float2(v[0], v[1]);
            *(float2*)&C[(size_t)(row + 8) * Nc + col] = make_float2(v[2], v[3]);
        }
    }
}

// ---------------- fp32 -> bf16 hi/lo split (5 tensors fused) ----------------
__device__ __forceinline__ void split4(const float4* src, __nv_bfloat162* hi,
                                       __nv_bfloat162* lo, int i)
{
    float4 v = src[i];
    __nv_bfloat16 h0 = __float2bfloat16(v.x);
    __nv_bfloat16 h1 = __float2bfloat16(v.y);
    __nv_bfloat16 h2 = __float2bfloat16(v.z);
    __nv_bfloat16 h3 = __float2bfloat16(v.w);
    hi[2 * i]     = __halves2bfloat162(h0, h1);
    hi[2 * i + 1] = __halves2bfloat162(h2, h3);
    lo[2 * i]     = __halves2bfloat162(
        __float2bfloat16(v.x - __bfloat162float(h0)),
        __float2bfloat16(v.y - __bfloat162float(h1)));
    lo[2 * i + 1] = __halves2bfloat162(
        __float2bfloat16(v.z - __bfloat162float(h2)),
        __float2bfloat16(v.w - __bfloat162float(h3)));
}

__global__ void cvt_split5_kernel(
    const float4* s1, __nv_bfloat162* h1, __nv_bfloat162* l1, int n1,
    const float4* s2, __nv_bfloat162* h2, __nv_bfloat162* l2, int n2,
    const float4* s3, __nv_bfloat162* h3, __nv_bfloat162* l3, int n3,
    const float4* s4, __nv_bfloat162* h4, __nv_bfloat162* l4, int n4,
    const float4* s5, __nv_bfloat162* h5, __nv_bfloat162* l5, int n5)
{
    int i = blockIdx.x * blockDim.x + threadIdx.x;
    if (i < n1) { split4(s1, h1, l1, i); return; } i -= n1;
    if (i < n2) { split4(s2, h2, l2, i); return; } i -= n2;
    if (i < n3) { split4(s3, h3, l3, i); return; } i -= n3;
    if (i < n4) { split4(s4, h4, l4, i); return; } i -= n4;
    if (i < n5) { split4(s5, h5, l5, i); }
}

// ---------------- reduce split-K partials + emit dt hi/lo -------------------
__global__ void reduce_dt_kernel(const float4* __restrict__ part,
                                 float4* __restrict__ dBCr,
                                 __nv_bfloat162* __restrict__ dthi,
                                 __nv_bfloat162* __restrict__ dtlo)
{
    int i = blockIdx.x * blockDim.x + threadIdx.x;   // over ML_*FP_/4
    if (i >= ML_ * FP_ / 4) return;
    const int STR = ML_ * FP_ / 4;
    float4 a = part[i];
    float4 b = part[i + STR];
    float4 c = part[i + 2 * STR];
    float4 d = part[i + 3 * STR];
    float4 s;
    s.x = (a.x + b.x) + (c.x + d.x);
    s.y = (a.y + b.y) + (c.y + d.y);
    s.z = (a.z + b.z) + (c.z + d.z);
    s.w = (a.w + b.w) + (c.w + d.w);
    dBCr[i] = s;

    int row = i >> 5;            // FP_/4 = 32
    int c4  = (i & 31) * 4;
    if (c4 < R_) {
        __nv_bfloat16 h0 = __float2bfloat16(s.x);
        __nv_bfloat16 h1 = __float2bfloat16(s.y);
        __nv_bfloat16 h2 = __float2bfloat16(s.z);
        __nv_bfloat16 h3 = __float2bfloat16(s.w);
        int o = (row * R_ + c4) >> 1;
        dthi[o]     = __halves2bfloat162(h0, h1);
        dthi[o + 1] = __halves2bfloat162(h2, h3);
        dtlo[o]     = __halves2bfloat162(
            __float2bfloat16(s.x - __bfloat162float(h0)),
            __float2bfloat16(s.y - __bfloat162float(h1)));
        dtlo[o + 1] = __halves2bfloat162(
            __float2bfloat16(s.z - __bfloat162float(h2)),
            __float2bfloat16(s.w - __bfloat162float(h3)));
    }
}

// ---------------- causal depthwise conv (K=4) + silu (+ hi/lo out) ----------
__global__ void conv_silu_kernel(const float* __restrict__ xz,
                                 const float* __restrict__ w,
                                 float* __restrict__ xc,
                                 __nv_bfloat16* __restrict__ xchi,
                                 __nv_bfloat16* __restrict__ xclo)
{
    int idx = blockIdx.x * blockDim.x + threadIdx.x;
    int e  = idx & (ED_ - 1);
    int bl = idx >> 11;
    int l  = bl & (L_ - 1);

    float acc = 0.f;
#pragma unroll
    for (int k = 0; k < 4; k++) {
        int ls = l - 3 + k;
        if (ls >= 0)
            acc = fmaf(w[e * 4 + k], xz[(size_t)(bl - 3 + k) * (2 * ED_) + e], acc);
    }
    float v = acc / (1.f + __expf(-acc));
    xc[idx] = v;
    __nv_bfloat16 hv = __float2bfloat16(v);
    xchi[idx] = hv;
    xclo[idx] = __float2bfloat16(v - __bfloat162float(hv));
}

// ============================================================================
// selective scan: smem-staged, coalesced, double-buffered cp.async.
// ============================================================================
#define SCH 64

__global__ __launch_bounds__(256) void scan2_kernel(
    const float* __restrict__ xz,
    const float* __restrict__ xc,
    const float* __restrict__ dBCr,
    const float* __restrict__ delta,
    const float* __restrict__ A_log,
    const float* __restrict__ Dp,
    __nv_bfloat16* __restrict__ yshi,
    __nv_bfloat16* __restrict__ yslo)
{
    __shared__ float sd[2][SCH][16];
    __shared__ float sx[2][SCH][16];
    __shared__ float sz[2][SCH][16];
    __shared__ float sbc[2][SCH][32];
    __shared__ float ysf[SCH][16];

    const int tid = threadIdx.x;
    const int e0  = blockIdx.x * 16;
    const int b   = blockIdx.y;
    const size_t rowBase = (size_t)b * L_;

    const int wid  = tid >> 5;
    const int lane = tid & 31;
    const int half = lane >> 4;
    const int n    = lane & 15;
    const int ch   = wid * 2 + half;
    const int e    = e0 + ch;

    const float a  = -expf(A_log[e * N_ + n]);
    const float dD = Dp[e];
    float h = 0.f;

    const int lr = tid >> 2;
    const int lc = (tid & 3) * 4;

    auto load_chunk = [&](int chk, int buf) {
        size_t l0 = rowBase + (size_t)chk * SCH;
        cp_async16(smem_u32(&sd[buf][lr][lc]),
                   &delta[(l0 + lr) * ED_ + e0 + lc]);
        cp_async16(smem_u32(&sx[buf][lr][lc]),
                   &xc[(l0 + lr) * ED_ + e0 + lc]);
        cp_async16(smem_u32(&sz[buf][lr][lc]),
                   &xz[(l0 + lr) * (2 * ED_) + ED_ + e0 + lc]);
#pragma unroll
        for (int i = 0; i < 2; i++) {
            int idx = tid + i * 256;
            int r = idx >> 3, c = (idx & 7) * 4;
            cp_async16(smem_u32(&sbc[buf][r][c]),
                       &dBCr[(l0 + r) * FP_ + R_ + c]);
        }
    };

    load_chunk(0, 0); CP_COMMIT();
    load_chunk(1, 1); CP_COMMIT();

    const int NCHUNK = L_ / SCH;
    for (int chk = 0; chk < NCHUNK; chk++) {
        const int buf = chk & 1;
        if (chk == NCHUNK - 1) { CP_WAIT(0); } else { CP_WAIT(1); }
        __syncthreads();

#pragma unroll 4
        for (int l = 0; l < SCH; l++) {
            float dl  = sd[buf][l][ch];
            float xcv = sx[buf][l][ch];
            float Bv  = sbc[buf][l][n];
            float Cv  = sbc[buf][l][16 + n];
            float dA  = __expf(dl * a);
            h = fmaf(h, dA, dl * Bv * xcv);
            float p = h * Cv;
            p += __shfl_xor_sync(0xffffffffu, p, 1);
            p += __shfl_xor_sync(0xffffffffu, p, 2);
            p += __shfl_xor_sync(0xffffffffu, p, 4);
            p += __shfl_xor_sync(0xffffffffu, p, 8);
            if (n == 0) {
                float y  = p + dD * xcv;
                float zv = sz[buf][l][ch];
                float sv = zv / (1.f + __expf(-zv));
                ysf[l][ch] = y * sv;
            }
        }
        __syncthreads();

        if (tid < 128) {
            int r = tid >> 1, hs = (tid & 1) * 8;
            __nv_bfloat162 hi4[4], lo4[4];
#pragma unroll
            for (int j = 0; j < 4; j++) {
                float v0 = ysf[r][hs + 2 * j];
                float v1 = ysf[r][hs + 2 * j + 1];
                __nv_bfloat16 h0 = __float2bfloat16(v0);
                __nv_bfloat16 h1 = __float2bfloat16(v1);
                hi4[j] = __halves2bfloat162(h0, h1);
                lo4[j] = __halves2bfloat162(
                    __float2bfloat16(v0 - __bfloat162float(h0)),
                    __float2bfloat16(v1 - __bfloat162float(h1)));
            }
            size_t off = (rowBase + (size_t)chk * SCH + r) * ED_ + e0 + hs;
            *(uint4*)&yshi[off] = *(uint4*)hi4;
            *(uint4*)&yslo[off] = *(uint4*)lo4;
        }

        if (chk + 2 < NCHUNK) { load_chunk(chk + 2, buf); CP_COMMIT(); }
    }
}

// ---------------- launch ----------------------------------------------------
extern "C" void kernel_launch(void* const* d_in, const int* in_sizes, int n_in,
                              void* d_out, int out_size)
{
    const float* x         = (const float*)d_in[0];
    const float* in_proj_w = (const float*)d_in[1];
    const float* conv_w    = (const float*)d_in[2];
    const float* x_proj_w  = (const float*)d_in[3];
    const float* dt_proj_w = (const float*)d_in[4];
    const float* dt_proj_b = (const float*)d_in[5];
    const float* A_log     = (const float*)d_in[6];
    const float* Dp        = (const float*)d_in[7];
    const float* out_proj_w= (const float*)d_in[8];
    float* out = (float*)d_out;

    float *xz, *xc, *delta, *dBCpart, *dBCr;
    cudaGetSymbolAddress((void**)&xz,      g_xz);
    cudaGetSymbolAddress((void**)&xc,      g_xc);
    cudaGetSymbolAddress((void**)&delta,   g_delta);
    cudaGetSymbolAddress((void**)&dBCpart, g_dBCpart);
    cudaGetSymbolAddress((void**)&dBCr,    g_dBCr);

    __nv_bfloat16 *xhi, *xlo, *wihi, *wilo, *yshi, *yslo, *wohi, *wolo;
    __nv_bfloat16 *xchi, *xclo, *wphi, *wplo, *dthi, *dtlo, *dtwhi, *dtwlo;
    cudaGetSymbolAddress((void**)&xhi,   g_xhi);
    cudaGetSymbolAddress((void**)&xlo,   g_xlo);
    cudaGetSymbolAddress((void**)&wihi,  g_wihi);
    cudaGetSymbolAddress((void**)&wilo,  g_wilo);
    cudaGetSymbolAddress((void**)&yshi,  g_yshi);
    cudaGetSymbolAddress((void**)&yslo,  g_yslo);
    cudaGetSymbolAddress((void**)&wohi,  g_wohi);
    cudaGetSymbolAddress((void**)&wolo,  g_wolo);
    cudaGetSymbolAddress((void**)&xchi,  g_xchi);
    cudaGetSymbolAddress((void**)&xclo,  g_xclo);
    cudaGetSymbolAddress((void**)&wphi,  g_wphi);
    cudaGetSymbolAddress((void**)&wplo,  g_wplo);
    cudaGetSymbolAddress((void**)&dthi,  g_dthi);
    cudaGetSymbolAddress((void**)&dtlo,  g_dtlo);
    cudaGetSymbolAddress((void**)&dtwhi, g_dtwhi);
    cudaGetSymbolAddress((void**)&dtwlo, g_dtwlo);

    static int smem_set = 0;
    if (!smem_set) {
        cudaFuncSetAttribute(gemm_mma_split<0>,
                             cudaFuncAttributeMaxDynamicSharedMemorySize, GSM_TOTAL);
        cudaFuncSetAttribute(gemm_mma_split<1>,
                             cudaFuncAttributeMaxDynamicSharedMemorySize, GSM_TOTAL);
        smem_set = 1;
    }

    // 0) fp32 -> bf16 hi/lo splits (x, in_w, out_w, x_proj_w, dt_proj_w)
    {
        int n1 = ML_ * DM_ / 4;
        int n2 = 2 * ED_ * DM_ / 4;
        int n3 = DM_ * ED_ / 4;
        int n4 = F_ * ED_ / 4;      // x_proj_w (valid 96 rows; pad rows stay 0)
        int n5 = ED_ * R_ / 4;      // dt_proj_w
        cvt_split5_kernel<<<(n1 + n2 + n3 + n4 + n5 + 255) / 256, 256>>>(
            (const float4*)x, (__nv_bfloat162*)xhi, (__nv_bfloat162*)xlo, n1,
            (const float4*)in_proj_w, (__nv_bfloat162*)wihi, (__nv_bfloat162*)wilo, n2,
            (const float4*)out_proj_w, (__nv_bfloat162*)wohi, (__nv_bfloat162*)wolo, n3,
            (const float4*)x_proj_w, (__nv_bfloat162*)wphi, (__nv_bfloat162*)wplo, n4,
            (const float4*)dt_proj_w, (__nv_bfloat162*)dtwhi, (__nv_bfloat162*)dtwlo, n5);
    }

    // 1) xz = x @ in_proj_w^T   [2048, 4096]
    gemm_mma_split<0><<<dim3(2 * ED_ / 128, ML_ / 128, 1), 256, GSM_TOTAL>>>(
        xhi, xlo, wihi, wilo, xz, 2 * ED_, DM_, DM_, nullptr, 0);

    // 2) xc = silu(conv(xz[:, :ED])) + hi/lo split
    conv_silu_kernel<<<(ML_ * ED_) / 256, 256>>>(xz, conv_w, xc, xchi, xclo);

    // 3) dBC partials = xc @ x_proj_w^T   (split-K=4, N padded to 128)
    gemm_mma_split<0><<<dim3(1, ML_ / 128, KSPLIT), 256, GSM_TOTAL>>>(
        xchi, xclo, wphi, wplo, dBCpart, FP_, ED_ / KSPLIT, ED_,
        nullptr, (size_t)ML_ * FP_);

    // 4) reduce partials -> dBCr; emit dt hi/lo
    reduce_dt_kernel<<<(ML_ * FP_ / 4 + 255) / 256, 256>>>(
        (const float4*)dBCpart, (float4*)dBCr,
        (__nv_bfloat162*)dthi, (__nv_bfloat162*)dtlo);

    // 5) delta = softplus(dt @ dt_proj_w^T + b)   [2048, 2048]
    gemm_mma_split<1><<<dim3(ED_ / 128, ML_ / 128, 1), 256, GSM_TOTAL>>>(
        dthi, dtlo, dtwhi, dtwlo, delta, ED_, R_, R_, dt_proj_b, 0);

    // 6) selective scan -> ys hi/lo
    scan2_kernel<<<dim3(ED_ / 16, B_), 256>>>(
        xz, xc, dBCr, delta, A_log, Dp, yshi, yslo);

    // 7) out = ys @ out_proj_w^T  [2048, 1024]
    gemm_mma_split<0><<<dim3(DM_ / 128, ML_ / 128, 1), 256, GSM_TOTAL>>>(
        yshi, yslo, wohi, wolo, out, DM_, ED_, ED_, nullptr, 0);
}

// round 7
// speedup vs baseline: 3.1696x; 1.0092x over previous
#include <cuda_runtime.h>
#include <cuda_bf16.h>
#include <math.h>
#include <stdint.h>

// Problem constants
#define B_    2
#define L_    1024
#define DM_   1024
#define ED_   2048
#define N_    16
#define R_    64
#define K_    4
#define ML_   (B_ * L_)        // 2048 rows
#define F_    96               // x_proj out cols (valid)
#define FP_   128              // padded
#define KSPLIT 4

// ---------------- scratch (device globals; no allocation allowed) ----------
__device__ float g_xz[ML_ * 2 * ED_];      // in_proj output  [2048, 4096]
__device__ float g_xc[ML_ * ED_];          // conv+silu fp32  [2048, 2048]
__device__ float g_delta[ML_ * ED_];       // softplus(dt_proj)
__device__ float g_dBCpart[KSPLIT * ML_ * FP_];  // split-K partials
__device__ float g_dBCr[ML_ * FP_];        // reduced dBC (padded lda 128)

// bf16 hi/lo split scratch (16B-aligned)
__device__ __align__(16) __nv_bfloat16 g_xhi[ML_ * DM_];
__device__ __align__(16) __nv_bfloat16 g_xlo[ML_ * DM_];
__device__ __align__(16) __nv_bfloat16 g_wihi[2 * ED_ * DM_];
__device__ __align__(16) __nv_bfloat16 g_wilo[2 * ED_ * DM_];
__device__ __align__(16) __nv_bfloat16 g_yshi[ML_ * ED_];
__device__ __align__(16) __nv_bfloat16 g_yslo[ML_ * ED_];
__device__ __align__(16) __nv_bfloat16 g_wohi[DM_ * ED_];
__device__ __align__(16) __nv_bfloat16 g_wolo[DM_ * ED_];
__device__ __align__(16) __nv_bfloat16 g_xchi[ML_ * ED_];
__device__ __align__(16) __nv_bfloat16 g_xclo[ML_ * ED_];
__device__ __align__(16) __nv_bfloat16 g_wphi[FP_ * ED_];   // rows 96..127 stay 0
__device__ __align__(16) __nv_bfloat16 g_wplo[FP_ * ED_];
__device__ __align__(16) __nv_bfloat16 g_dthi[ML_ * R_];
__device__ __align__(16) __nv_bfloat16 g_dtlo[ML_ * R_];
__device__ __align__(16) __nv_bfloat16 g_dtwhi[ED_ * R_];
__device__ __align__(16) __nv_bfloat16 g_dtwlo[ED_ * R_];

// ============================================================================
// helpers
// ============================================================================
__device__ __forceinline__ uint32_t smem_u32(const void* p) {
    uint32_t a;
    asm("{ .reg .u64 t; cvta.to.shared.u64 t, %1; cvt.u32.u64 %0, t; }"
        : "=r"(a) : "l"(p));
    return a;
}

__device__ __forceinline__ void cp_async16(uint32_t saddr, const void* gaddr) {
    asm volatile("cp.async.cg.shared.global [%0], [%1], 16;"
                 :: "r"(saddr), "l"(gaddr));
}
#define CP_COMMIT() asm volatile("cp.async.commit_group;" ::: "memory")
#define CP_WAIT(n)  asm volatile("cp.async.wait_group %0;" :: "n"(n) : "memory")

__device__ __forceinline__ void mma16816(float* d, const uint32_t* a,
                                         const uint32_t* b) {
    asm volatile(
        "mma.sync.aligned.m16n8k16.row.col.f32.bf16.bf16.f32 "
        "{%0,%1,%2,%3}, {%4,%5,%6,%7}, {%8,%9}, {%0,%1,%2,%3};"
        : "+f"(d[0]), "+f"(d[1]), "+f"(d[2]), "+f"(d[3])
        : "r"(a[0]), "r"(a[1]), "r"(a[2]), "r"(a[3]),
          "r"(b[0]), "r"(b[1]));
}

__device__ __forceinline__ void ldsm4(uint32_t* r, uint32_t addr) {
    asm volatile("ldmatrix.sync.aligned.m8n8.x4.shared.b16 {%0,%1,%2,%3}, [%4];"
                 : "=r"(r[0]), "=r"(r[1]), "=r"(r[2]), "=r"(r[3])
                 : "r"(addr));
}

// ============================================================================
// bf16-split mma.sync GEMM (universal):
//   C[z][M,N] += Ahi/lo[M, kbase:kbase+Ksub] * (Bhi/lo[N, ...])^T
// CTA tile 128x128; K staged by 16 in a 4-deep cp.async ring (ONE barrier per
// stage). 8 warps (2Mx4N), warp tile 64x32. PITCH=24 bf16 (48B rows) is
// LDSM-conflict-free. grid.z slices K deterministically. ACT=1: softplus+bias.
// ============================================================================
#define PITCH 24
#define TILE_B (128 * PITCH * 2)          // 6144 B
#define STAGE_B (4 * TILE_B)              // 24576 B
#define NSTAGE 4
#define GSM_TOTAL (NSTAGE * STAGE_B)      // 98304 B

template <int ACT>
__global__ __launch_bounds__(256, 2) void gemm_mma_split(
    const __nv_bfloat16* __restrict__ Ahi, const __nv_bfloat16* __restrict__ Alo,
    const __nv_bfloat16* __restrict__ Bhi, const __nv_bfloat16* __restrict__ Blo,
    float* __restrict__ C, int Nc, int Ksub, int Kfull,
    const float* __restrict__ bias, size_t partStride)
{
    extern __shared__ char smem[];
    const uint32_t sbase = smem_u32(smem);

    const int tid  = threadIdx.x;
    const int wid  = tid >> 5;
    const int lane = tid & 31;
    const int gid  = lane >> 2;
    const int tq   = lane & 3;
    const int wm   = (wid >> 2) * 64;
    const int wn   = (wid & 3) * 32;
    const int m0 = blockIdx.y * 128;
    const int n0 = blockIdx.x * 128;
    const int kbase = blockIdx.z * Ksub;

    const int t7  = lane & 7;
    const int grp = lane >> 3;
    const int aRow = (grp & 1) * 8 + t7;
    const int aCol = (grp >> 1) * 8;
    const int bRow = (grp >> 1) * 8 + t7;
    const int bCol = (grp & 1) * 8;

    const __nv_bfloat16* srcs[4] = {
        Ahi + (size_t)m0 * Kfull + kbase, Alo + (size_t)m0 * Kfull + kbase,
        Bhi + (size_t)n0 * Kfull + kbase, Blo + (size_t)n0 * Kfull + kbase };

    C += (size_t)blockIdx.z * partStride;

    const int S = Ksub / 16;

    float acc[4][4][4];
#pragma unroll
    for (int i = 0; i < 4; i++)
#pragma unroll
        for (int j = 0; j < 4; j++)
#pragma unroll
            for (int r = 0; r < 4; r++) acc[i][j][r] = 0.f;

    // loader: per tile 128 rows x 32B (2 chunks); one chunk per thread per tile
    const int lrow = tid >> 1;        // 0..127
    const int lch  = tid & 1;         // 0..1
    auto load_stage = [&](int s, int buf) {
        const int k0 = s * 16;
        char* sb = smem + buf * STAGE_B;
        uint32_t sa = smem_u32(sb) + lrow * (PITCH * 2) + lch * 16;
#pragma unroll
        for (int t = 0; t < 4; t++) {
            const __nv_bfloat16* src = srcs[t] + (size_t)lrow * Kfull + k0 + lch * 8;
            cp_async16(sa + t * TILE_B, src);
        }
    };

    auto compute = [&](int buf) {
        const uint32_t sb  = sbase + buf * STAGE_B;
        const uint32_t sBh = sb + 2 * TILE_B;
        uint32_t bh[2][4], bl[2][4];
#pragma unroll
        for (int p = 0; p < 2; p++) {
            uint32_t baddr = sBh + ((wn + p * 16 + bRow) * PITCH + bCol) * 2;
            ldsm4(bh[p], baddr);
            ldsm4(bl[p], baddr + TILE_B);
        }
#pragma unroll
        for (int mt = 0; mt < 4; mt++) {
            uint32_t aaddr = sb + ((wm + mt * 16 + aRow) * PITCH + aCol) * 2;
            uint32_t ah[4], al[4];
            ldsm4(ah, aaddr);
            ldsm4(al, aaddr + TILE_B);
#pragma unroll
            for (int nt = 0; nt < 4; nt++) {
                const uint32_t* bbh = &bh[nt >> 1][(nt & 1) * 2];
                const uint32_t* bbl = &bl[nt >> 1][(nt & 1) * 2];
                mma16816(acc[mt][nt], ah, bbh);
                mma16816(acc[mt][nt], ah, bbl);
                mma16816(acc[mt][nt], al, bbh);
            }
        }
    };

    // ---- 4-stage ring, single barrier per stage ----------------------------
#pragma unroll
    for (int i = 0; i < NSTAGE - 1; i++) {
        if (i < S) load_stage(i, i);
        CP_COMMIT();
    }
    for (int s = 0; s < S; s++) {
        CP_WAIT(NSTAGE - 2);
        __syncthreads();
        compute(s & (NSTAGE - 1));
        if (s + NSTAGE - 1 < S)
            load_stage(s + NSTAGE - 1, (s + NSTAGE - 1) & (NSTAGE - 1));
        CP_COMMIT();
    }

    // ---- epilogue -----------------------------------------------------------
#pragma unroll
    for (int mt = 0; mt < 4; mt++) {
        int row = m0 + wm + mt * 16 + gid;
#pragma unroll
        for (int nt = 0; nt < 4; nt++) {
            int col = n0 + wn + nt * 8 + tq * 2;
            float v[4] = {acc[mt][nt][0], acc[mt][nt][1],
                          acc[mt][nt][2], acc[mt][nt][3]};
            if (ACT == 1) {
                float b0 = bias[col], b1 = bias[col + 1];
                v[0] += b0; v[1] += b1; v[2] += b0; v[3] += b1;
#pragma unroll
                for (int r = 0; r < 4; r++)
                    v[r] = (v[r] > 20.f) ? v[r] : log1pf(expf(v[r]));
            }
            *(float2*)&C[(size_t)row * Nc + col] = make_float2(v[0], v[1]);
            *(float2*)&C[(size_t)(row + 8) * Nc + col] = make_float2(v[2], v[3]);
        }
    }
}

// ---------------- fp32 -> bf16 hi/lo split (5 tensors fused) ----------------
__device__ __forceinline__ void split4(const float4* src, __nv_bfloat162* hi,
                                       __nv_bfloat162* lo, int i)
{
    float4 v = src[i];
    __nv_bfloat16 h0 = __float2bfloat16(v.x);
    __nv_bfloat16 h1 = __float2bfloat16(v.y);
    __nv_bfloat16 h2 = __float2bfloat16(v.z);
    __nv_bfloat16 h3 = __float2bfloat16(v.w);
    hi[2 * i]     = __halves2bfloat162(h0, h1);
    hi[2 * i + 1] = __halves2bfloat162(h2, h3);
    lo[2 * i]     = __halves2bfloat162(
        __float2bfloat16(v.x - __bfloat162float(h0)),
        __float2bfloat16(v.y - __bfloat162float(h1)));
    lo[2 * i + 1] = __halves2bfloat162(
        __float2bfloat16(v.z - __bfloat162float(h2)),
        __float2bfloat16(v.w - __bfloat162float(h3)));
}

__global__ void cvt_split5_kernel(
    const float4* s1, __nv_bfloat162* h1, __nv_bfloat162* l1, int n1,
    const float4* s2, __nv_bfloat162* h2, __nv_bfloat162* l2, int n2,
    const float4* s3, __nv_bfloat162* h3, __nv_bfloat162* l3, int n3,
    const float4* s4, __nv_bfloat162* h4, __nv_bfloat162* l4, int n4,
    const float4* s5, __nv_bfloat162* h5, __nv_bfloat162* l5, int n5)
{
    int i = blockIdx.x * blockDim.x + threadIdx.x;
    if (i < n1) { split4(s1, h1, l1, i); return; } i -= n1;
    if (i < n2) { split4(s2, h2, l2, i); return; } i -= n2;
    if (i < n3) { split4(s3, h3, l3, i); return; } i -= n3;
    if (i < n4) { split4(s4, h4, l4, i); return; } i -= n4;
    if (i < n5) { split4(s5, h5, l5, i); }
}

// ---------------- reduce split-K partials + emit dt hi/lo -------------------
__global__ void reduce_dt_kernel(const float4* __restrict__ part,
                                 float4* __restrict__ dBCr,
                                 __nv_bfloat162* __restrict__ dthi,
                                 __nv_bfloat162* __restrict__ dtlo)
{
    int i = blockIdx.x * blockDim.x + threadIdx.x;   // over ML_*FP_/4
    if (i >= ML_ * FP_ / 4) return;
    const int STR = ML_ * FP_ / 4;
    float4 a = part[i];
    float4 b = part[i + STR];
    float4 c = part[i + 2 * STR];
    float4 d = part[i + 3 * STR];
    float4 s;
    s.x = (a.x + b.x) + (c.x + d.x);
    s.y = (a.y + b.y) + (c.y + d.y);
    s.z = (a.z + b.z) + (c.z + d.z);
    s.w = (a.w + b.w) + (c.w + d.w);
    dBCr[i] = s;

    int row = i >> 5;            // FP_/4 = 32
    int c4  = (i & 31) * 4;
    if (c4 < R_) {
        __nv_bfloat16 h0 = __float2bfloat16(s.x);
        __nv_bfloat16 h1 = __float2bfloat16(s.y);
        __nv_bfloat16 h2 = __float2bfloat16(s.z);
        __nv_bfloat16 h3 = __float2bfloat16(s.w);
        int o = (row * R_ + c4) >> 1;
        dthi[o]     = __halves2bfloat162(h0, h1);
        dthi[o + 1] = __halves2bfloat162(h2, h3);
        dtlo[o]     = __halves2bfloat162(
            __float2bfloat16(s.x - __bfloat162float(h0)),
            __float2bfloat16(s.y - __bfloat162float(h1)));
        dtlo[o + 1] = __halves2bfloat162(
            __float2bfloat16(s.z - __bfloat162float(h2)),
            __float2bfloat16(s.w - __bfloat162float(h3)));
    }
}

// ---------------- causal depthwise conv (K=4) + silu (+ hi/lo out) ----------
__global__ void conv_silu_kernel(const float* __restrict__ xz,
                                 const float* __restrict__ w,
                                 float* __restrict__ xc,
                                 __nv_bfloat16* __restrict__ xchi,
                                 __nv_bfloat16* __restrict__ xclo)
{
    int idx = blockIdx.x * blockDim.x + threadIdx.x;
    int e  = idx & (ED_ - 1);
    int bl = idx >> 11;
    int l  = bl & (L_ - 1);

    float acc = 0.f;
#pragma unroll
    for (int k = 0; k < 4; k++) {
        int ls = l - 3 + k;
        if (ls >= 0)
            acc = fmaf(w[e * 4 + k], xz[(size_t)(bl - 3 + k) * (2 * ED_) + e], acc);
    }
    float v = acc / (1.f + __expf(-acc));
    xc[idx] = v;
    __nv_bfloat16 hv = __float2bfloat16(v);
    xchi[idx] = hv;
    xclo[idx] = __float2bfloat16(v - __bfloat162float(hv));
}

// ============================================================================
// selective scan: smem-staged, coalesced, double-buffered cp.async.
// ============================================================================
#define SCH 64

__global__ __launch_bounds__(256) void scan2_kernel(
    const float* __restrict__ xz,
    const float* __restrict__ xc,
    const float* __restrict__ dBCr,
    const float* __restrict__ delta,
    const float* __restrict__ A_log,
    const float* __restrict__ Dp,
    __nv_bfloat16* __restrict__ yshi,
    __nv_bfloat16* __restrict__ yslo)
{
    __shared__ float sd[2][SCH][16];
    __shared__ float sx[2][SCH][16];
    __shared__ float sz[2][SCH][16];
    __shared__ float sbc[2][SCH][32];
    __shared__ float ysf[SCH][16];

    const int tid = threadIdx.x;
    const int e0  = blockIdx.x * 16;
    const int b   = blockIdx.y;
    const size_t rowBase = (size_t)b * L_;

    const int wid  = tid >> 5;
    const int lane = tid & 31;
    const int half = lane >> 4;
    const int n    = lane & 15;
    const int ch   = wid * 2 + half;
    const int e    = e0 + ch;

    const float a  = -expf(A_log[e * N_ + n]);
    const float dD = Dp[e];
    float h = 0.f;

    const int lr = tid >> 2;
    const int lc = (tid & 3) * 4;

    auto load_chunk = [&](int chk, int buf) {
        size_t l0 = rowBase + (size_t)chk * SCH;
        cp_async16(smem_u32(&sd[buf][lr][lc]),
                   &delta[(l0 + lr) * ED_ + e0 + lc]);
        cp_async16(smem_u32(&sx[buf][lr][lc]),
                   &xc[(l0 + lr) * ED_ + e0 + lc]);
        cp_async16(smem_u32(&sz[buf][lr][lc]),
                   &xz[(l0 + lr) * (2 * ED_) + ED_ + e0 + lc]);
#pragma unroll
        for (int i = 0; i < 2; i++) {
            int idx = tid + i * 256;
            int r = idx >> 3, c = (idx & 7) * 4;
            cp_async16(smem_u32(&sbc[buf][r][c]),
                       &dBCr[(l0 + r) * FP_ + R_ + c]);
        }
    };

    load_chunk(0, 0); CP_COMMIT();
    load_chunk(1, 1); CP_COMMIT();

    const int NCHUNK = L_ / SCH;
    for (int chk = 0; chk < NCHUNK; chk++) {
        const int buf = chk & 1;
        if (chk == NCHUNK - 1) { CP_WAIT(0); } else { CP_WAIT(1); }
        __syncthreads();

#pragma unroll 4
        for (int l = 0; l < SCH; l++) {
            float dl  = sd[buf][l][ch];
            float xcv = sx[buf][l][ch];
            float Bv  = sbc[buf][l][n];
            float Cv  = sbc[buf][l][16 + n];
            float dA  = __expf(dl * a);
            h = fmaf(h, dA, dl * Bv * xcv);
            float p = h * Cv;
            p += __shfl_xor_sync(0xffffffffu, p, 1);
            p += __shfl_xor_sync(0xffffffffu, p, 2);
            p += __shfl_xor_sync(0xffffffffu, p, 4);
            p += __shfl_xor_sync(0xffffffffu, p, 8);
            if (n == 0) {
                float y  = p + dD * xcv;
                float zv = sz[buf][l][ch];
                float sv = zv / (1.f + __expf(-zv));
                ysf[l][ch] = y * sv;
            }
        }
        __syncthreads();

        if (tid < 128) {
            int r = tid >> 1, hs = (tid & 1) * 8;
            __nv_bfloat162 hi4[4], lo4[4];
#pragma unroll
            for (int j = 0; j < 4; j++) {
                float v0 = ysf[r][hs + 2 * j];
                float v1 = ysf[r][hs + 2 * j + 1];
                __nv_bfloat16 h0 = __float2bfloat16(v0);
                __nv_bfloat16 h1 = __float2bfloat16(v1);
                hi4[j] = __halves2bfloat162(h0, h1);
                lo4[j] = __halves2bfloat162(
                    __float2bfloat16(v0 - __bfloat162float(h0)),
                    __float2bfloat16(v1 - __bfloat162float(h1)));
            }
            size_t off = (rowBase + (size_t)chk * SCH + r) * ED_ + e0 + hs;
            *(uint4*)&yshi[off] = *(uint4*)hi4;
            *(uint4*)&yslo[off] = *(uint4*)lo4;
        }

        if (chk + 2 < NCHUNK) { load_chunk(chk + 2, buf); CP_COMMIT(); }
    }
}

// ---------------- launch ----------------------------------------------------
extern "C" void kernel_launch(void* const* d_in, const int* in_sizes, int n_in,
                              void* d_out, int out_size)
{
    const float* x         = (const float*)d_in[0];
    const float* in_proj_w = (const float*)d_in[1];
    const float* conv_w    = (const float*)d_in[2];
    const float* x_proj_w  = (const float*)d_in[3];
    const float* dt_proj_w = (const float*)d_in[4];
    const float* dt_proj_b = (const float*)d_in[5];
    const float* A_log     = (const float*)d_in[6];
    const float* Dp        = (const float*)d_in[7];
    const float* out_proj_w= (const float*)d_in[8];
    float* out = (float*)d_out;

    float *xz, *xc, *delta, *dBCpart, *dBCr;
    cudaGetSymbolAddress((void**)&xz,      g_xz);
    cudaGetSymbolAddress((void**)&xc,      g_xc);
    cudaGetSymbolAddress((void**)&delta,   g_delta);
    cudaGetSymbolAddress((void**)&dBCpart, g_dBCpart);
    cudaGetSymbolAddress((void**)&dBCr,    g_dBCr);

    __nv_bfloat16 *xhi, *xlo, *wihi, *wilo, *yshi, *yslo, *wohi, *wolo;
    __nv_bfloat16 *xchi, *xclo, *wphi, *wplo, *dthi, *dtlo, *dtwhi, *dtwlo;
    cudaGetSymbolAddress((void**)&xhi,   g_xhi);
    cudaGetSymbolAddress((void**)&xlo,   g_xlo);
    cudaGetSymbolAddress((void**)&wihi,  g_wihi);
    cudaGetSymbolAddress((void**)&wilo,  g_wilo);
    cudaGetSymbolAddress((void**)&yshi,  g_yshi);
    cudaGetSymbolAddress((void**)&yslo,  g_yslo);
    cudaGetSymbolAddress((void**)&wohi,  g_wohi);
    cudaGetSymbolAddress((void**)&wolo,  g_wolo);
    cudaGetSymbolAddress((void**)&xchi,  g_xchi);
    cudaGetSymbolAddress((void**)&xclo,  g_xclo);
    cudaGetSymbolAddress((void**)&wphi,  g_wphi);
    cudaGetSymbolAddress((void**)&wplo,  g_wplo);
    cudaGetSymbolAddress((void**)&dthi,  g_dthi);
    cudaGetSymbolAddress((void**)&dtlo,  g_dtlo);
    cudaGetSymbolAddress((void**)&dtwhi, g_dtwhi);
    cudaGetSymbolAddress((void**)&dtwlo, g_dtwlo);

    static int smem_set = 0;
    if (!smem_set) {
        cudaFuncSetAttribute(gemm_mma_split<0>,
                             cudaFuncAttributeMaxDynamicSharedMemorySize, GSM_TOTAL);
        cudaFuncSetAttribute(gemm_mma_split<1>,
                             cudaFuncAttributeMaxDynamicSharedMemorySize, GSM_TOTAL);
        smem_set = 1;
    }

    // 0) fp32 -> bf16 hi/lo splits (x, in_w, out_w, x_proj_w, dt_proj_w)
    {
        int n1 = ML_ * DM_ / 4;
        int n2 = 2 * ED_ * DM_ / 4;
        int n3 = DM_ * ED_ / 4;
        int n4 = F_ * ED_ / 4;
        int n5 = ED_ * R_ / 4;
        cvt_split5_kernel<<<(n1 + n2 + n3 + n4 + n5 + 255) / 256, 256>>>(
            (const float4*)x, (__nv_bfloat162*)xhi, (__nv_bfloat162*)xlo, n1,
            (const float4*)in_proj_w, (__nv_bfloat162*)wihi, (__nv_bfloat162*)wilo, n2,
            (const float4*)out_proj_w, (__nv_bfloat162*)wohi, (__nv_bfloat162*)wolo, n3,
            (const float4*)x_proj_w, (__nv_bfloat162*)wphi, (__nv_bfloat162*)wplo, n4,
            (const float4*)dt_proj_w, (__nv_bfloat162*)dtwhi, (__nv_bfloat162*)dtwlo, n5);
    }

    // 1) xz = x @ in_proj_w^T   [2048, 4096]
    gemm_mma_split<0><<<dim3(2 * ED_ / 128, ML_ / 128, 1), 256, GSM_TOTAL>>>(
        xhi, xlo, wihi, wilo, xz, 2 * ED_, DM_, DM_, nullptr, 0);

    // 2) xc = silu(conv(xz[:, :ED])) + hi/lo split
    conv_silu_kernel<<<(ML_ * ED_) / 256, 256>>>(xz, conv_w, xc, xchi, xclo);

    // 3) dBC partials = xc @ x_proj_w^T   (split-K=4, N padded to 128)
    gemm_mma_split<0><<<dim3(1, ML_ / 128, KSPLIT), 256, GSM_TOTAL>>>(
        xchi, xclo, wphi, wplo, dBCpart, FP_, ED_ / KSPLIT, ED_,
        nullptr, (size_t)ML_ * FP_);

    // 4) reduce partials -> dBCr; emit dt hi/lo
    reduce_dt_kernel<<<(ML_ * FP_ / 4 + 255) / 256, 256>>>(
        (const float4*)dBCpart, (float4*)dBCr,
        (__nv_bfloat162*)dthi, (__nv_bfloat162*)dtlo);

    // 5) delta = softplus(dt @ dt_proj_w^T + b)   [2048, 2048]
    gemm_mma_split<1><<<dim3(ED_ / 128, ML_ / 128, 1), 256, GSM_TOTAL>>>(
        dthi, dtlo, dtwhi, dtwlo, delta, ED_, R_, R_, dt_proj_b, 0);

    // 6) selective scan -> ys hi/lo
    scan2_kernel<<<dim3(ED_ / 16, B_), 256>>>(
        xz, xc, dBCr, delta, A_log, Dp, yshi, yslo);

    // 7) out = ys @ out_proj_w^T  [2048, 1024]
    gemm_mma_split<0><<<dim3(DM_ / 128, ML_ / 128, 1), 256, GSM_TOTAL>>>(
        yshi, yslo, wohi, wolo, out, DM_, ED_, ED_, nullptr, 0);
}